// round 5
// baseline (speedup 1.0000x reference)
#include <cuda_runtime.h>

// ---------------------------------------------------------------------------
// AdaMix: self-paced patch mixing — 3-kernel version (R5).
//   K1: dice-loss partial sums (32 segments/sample, fully front-batched loads)
//       + per-patch conf means, float4-vectorized.
//   K2 (tiny): per-sample reduce -> k/sign -> stable ranks -> g_map.
//   K3: lean gather/scatter, 2 rows per thread, no smem, no syncs.
// ---------------------------------------------------------------------------

#define Bn    64
#define Cn    3
#define IMGn  256
#define NCn   4
#define Hn    32
#define Pn    64
#define TOPKn 16
#define NPIX  (IMGn * IMGn)   // 65536
#define NP4   (NPIX >> 2)     // 16384 float4 per plane
#define NSEG  32              // dice segments per sample

// scratch (allocation-free: __device__ globals)
// layout per (b,seg): [0:4)=inter, [4:8)=ssum, [8:12)=cnt
__device__ double g_part[Bn][NSEG][12];
__device__ float  g_omean[Bn][Pn];
__device__ float  g_amean[Bn][Pn];
__device__ int    g_map[Bn][Pn];   // bit8 = use-augmented, low 8 bits = src patch

// --- K1: dice partials (blocks 0..2047) + patch means (blocks 2048..3071) ---
__global__ void __launch_bounds__(256, 8)
k_stage1(const float* __restrict__ pred,
         const int*   __restrict__ olabel,
         const float* __restrict__ oconf,
         const float* __restrict__ aconf) {
    const int blk = blockIdx.x;
    const int t   = threadIdx.x;

    if (blk < Bn * NSEG) {
        // ---- dice partial sums: b = blk>>5, segment = blk&31 (2048 pixels)
        const int b   = blk >> 5;
        const int seg = blk & (NSEG - 1);
        const float4* p4 = (const float4*)(pred + (size_t)b * NCn * NPIX);
        const int4*   l4 = (const int4*)(olabel + (size_t)b * NPIX);
        const int i4a = seg * 512 + t;         // two float4 groups per thread
        const int i4b = i4a + 256;

        // front-batch all 10 loads
        float4 a0 = p4[i4a];
        float4 a1 = p4[i4a + NP4];
        float4 a2 = p4[i4a + 2 * NP4];
        float4 a3 = p4[i4a + 3 * NP4];
        int4   lA = l4[i4a];
        float4 b0 = p4[i4b];
        float4 b1 = p4[i4b + NP4];
        float4 b2 = p4[i4b + 2 * NP4];
        float4 b3 = p4[i4b + 3 * NP4];
        int4   lB = l4[i4b];

        float ssum[NCn]  = {0, 0, 0, 0};
        float inter[NCn] = {0, 0, 0, 0};
        float cnt[NCn]   = {0, 0, 0, 0};

        #pragma unroll
        for (int g = 0; g < 2; g++) {
            float x0[4], x1[4], x2[4], x3[4];
            int   lv[4];
            if (g == 0) {
                x0[0]=a0.x; x0[1]=a0.y; x0[2]=a0.z; x0[3]=a0.w;
                x1[0]=a1.x; x1[1]=a1.y; x1[2]=a1.z; x1[3]=a1.w;
                x2[0]=a2.x; x2[1]=a2.y; x2[2]=a2.z; x2[3]=a2.w;
                x3[0]=a3.x; x3[1]=a3.y; x3[2]=a3.z; x3[3]=a3.w;
                lv[0]=lA.x; lv[1]=lA.y; lv[2]=lA.z; lv[3]=lA.w;
            } else {
                x0[0]=b0.x; x0[1]=b0.y; x0[2]=b0.z; x0[3]=b0.w;
                x1[0]=b1.x; x1[1]=b1.y; x1[2]=b1.z; x1[3]=b1.w;
                x2[0]=b2.x; x2[1]=b2.y; x2[2]=b2.z; x2[3]=b2.w;
                x3[0]=b3.x; x3[1]=b3.y; x3[2]=b3.z; x3[3]=b3.w;
                lv[0]=lB.x; lv[1]=lB.y; lv[2]=lB.z; lv[3]=lB.w;
            }
            #pragma unroll
            for (int j = 0; j < 4; j++) {
                // inputs ~N(0,1): exp without max-shift is safe in fp32
                float e0 = __expf(x0[j]), e1 = __expf(x1[j]);
                float e2 = __expf(x2[j]), e3 = __expf(x3[j]);
                float inv = __frcp_rn((e0 + e1) + (e2 + e3));
                float s[NCn] = {e0 * inv, e1 * inv, e2 * inv, e3 * inv};
                const int lab = lv[j];
                #pragma unroll
                for (int c = 0; c < NCn; c++) {
                    float f = (lab == c) ? 1.0f : 0.0f;
                    ssum[c]  += s[c];
                    inter[c] = fmaf(f, s[c], inter[c]);
                    cnt[c]   += f;
                }
            }
        }

        // deterministic reduce: warp (double) -> shared -> thread 0
        __shared__ double sw[8][12];
        const int lane = t & 31, wid = t >> 5;
        #pragma unroll
        for (int c = 0; c < NCn; c++) {
            double vi = (double)inter[c];
            double vs = (double)ssum[c];
            double vc = (double)cnt[c];
            #pragma unroll
            for (int o = 16; o > 0; o >>= 1) {
                vi += __shfl_down_sync(0xffffffffu, vi, o);
                vs += __shfl_down_sync(0xffffffffu, vs, o);
                vc += __shfl_down_sync(0xffffffffu, vc, o);
            }
            if (lane == 0) { sw[wid][c] = vi; sw[wid][4 + c] = vs; sw[wid][8 + c] = vc; }
        }
        __syncthreads();
        if (t < 12) {
            double v = 0.0;
            #pragma unroll
            for (int w = 0; w < 8; w++) v += sw[w][t];
            g_part[b][seg][t] = v;
        }
    } else {
        // ---- patch means: m in [0,1024): b = m>>4, src = (m>>3)&1, band = m&7
        const int m    = blk - Bn * NSEG;
        const int b    = m >> 4;
        const int s    = (m >> 3) & 1;
        const int band = m & 7;
        const float4* src = (const float4*)((s ? aconf : oconf)
                              + (size_t)b * NPIX + band * Hn * IMGn);
        float acc = 0.0f;
        #pragma unroll
        for (int it = 0; it < 8; it++) {
            float4 v = src[it * 256 + t];
            acc += (v.x + v.y) + (v.z + v.w);
        }
        __shared__ float sacc[256];
        sacc[t] = acc;
        __syncthreads();
        if (t < 8) {
            float tot = 0.0f;
            #pragma unroll
            for (int g = 0; g < 4; g++)
                #pragma unroll
                for (int j = 0; j < 8; j++)
                    tot += sacc[g * 64 + t * 8 + j];
            float mean = tot * (1.0f / (Hn * Hn));
            if (s) g_amean[b][band * 8 + t] = mean;
            else   g_omean[b][band * 8 + t] = mean;
        }
    }
}

// --- K2 (tiny): per-sample loss -> k/sign -> stable ranks -> g_map ---------
__global__ void k_map() {
    const int b = blockIdx.x;
    const int t = threadIdx.x;   // 64 threads

    __shared__ double s12[12];
    __shared__ float  s_ko[Pn], s_ka[Pn];
    __shared__ int    s_oidx[Pn], s_aidx[Pn];
    __shared__ int    s_k;
    __shared__ float  s_sign;

    if (t < 12) {
        double v = 0.0;
        #pragma unroll
        for (int s = 0; s < NSEG; s++) v += g_part[b][s][t];
        s12[t] = v;
    }
    __syncthreads();
    if (t == 0) {
        double dice = 0.0;
        #pragma unroll
        for (int c = 0; c < NCn; c++) {
            double un = s12[4 + c] + s12[8 + c];
            dice += 2.0 * s12[c] / (un + 1e-5);
        }
        float lossf = (float)(1.0 - dice * 0.25);
        bool  mask  = lossf < 1.0f;                       // AGE = 1.0
        float spw   = 1.0f - lossf / (1.0f + 1e-5f);
        s_k    = min(TOPKn, (int)fabsf(truncf((float)TOPKn * spw)));
        s_sign = mask ? -1.0f : 1.0f;
    }
    __syncthreads();

    s_ko[t] =  s_sign * g_omean[b][t];
    s_ka[t] = -s_sign * g_amean[b][t];
    __syncthreads();

    float mo = s_ko[t], ma = s_ka[t];
    int ro = 0, ra = 0;
    #pragma unroll
    for (int q = 0; q < Pn; q++) {
        float vo = s_ko[q]; ro += (vo < mo) || (vo == mo && q < t);
        float va = s_ka[q]; ra += (va < ma) || (va == ma && q < t);
    }
    s_oidx[ro] = t;
    s_aidx[ra] = t;
    __syncthreads();

    int dest = s_oidx[t];
    g_map[b][dest] = (t < s_k) ? (s_aidx[t] | 256) : dest;
}

// --- K3: lean gather/scatter. Block = (b, 8-row band); thread does 2 rows. --
__global__ void k_scatter(const float* __restrict__ oimg,
                          const float* __restrict__ aimg,
                          const int*   __restrict__ olab,
                          const int*   __restrict__ alab,
                          const float* __restrict__ oconf,
                          const float* __restrict__ aconf,
                          float* __restrict__ out) {
    const int t    = threadIdx.x;
    const int b    = blockIdx.x >> 5;
    const int band = blockIdx.x & 31;       // 8 dest rows: band*8 .. band*8+7

    const int r  = t >> 6;                  // 0..3
    const int c4 = t & 63;
    const int x  = c4 << 2;
    const int y0 = (band << 3) + r;         // rows y0 and y0+4, same patch row
    const int p  = ((y0 >> 5) << 3) | (x >> 5);

    const int v    = __ldg(&g_map[b][p]);
    const int q    = v & 255;
    const bool sel = (v & 256) != 0;
    const int sy0 = ((q >> 3) << 5) | (y0 & 31);
    const int sx  = ((q & 7)  << 5) | (x & 31);

    const size_t d0 = (size_t)y0 * 64 + c4;              // within plane (float4)
    const size_t d1 = d0 + 4 * 64;
    const size_t s0 = ((size_t)sy0 * IMGn + sx) >> 2;
    const size_t s1 = s0 + 4 * 64;
    const size_t bpl4 = (size_t)b * NP4;

    const float4* img4 = (const float4*)(sel ? aimg : oimg);
    const int4*   lab4 = (const int4*)  (sel ? alab : olab);
    const float4* cnf4 = (const float4*)(sel ? aconf : oconf);
    float4* o4 = (float4*)out;

    const size_t ib4 = (size_t)b * Cn * NP4;
    const size_t LB4 = (size_t)Bn * Cn * NP4;        // label plane base (float4)
    const size_t CB4 = LB4 + (size_t)Bn * NP4;       // conf plane base

    // issue all 10 loads first (max MLP), then all 10 stores
    float4 i0a = img4[ib4 + 0 * NP4 + s0];
    float4 i1a = img4[ib4 + 1 * NP4 + s0];
    float4 i2a = img4[ib4 + 2 * NP4 + s0];
    float4 i0b = img4[ib4 + 0 * NP4 + s1];
    float4 i1b = img4[ib4 + 1 * NP4 + s1];
    float4 i2b = img4[ib4 + 2 * NP4 + s1];
    int4   lva = lab4[bpl4 + s0];
    int4   lvb = lab4[bpl4 + s1];
    float4 cva = cnf4[bpl4 + s0];
    float4 cvb = cnf4[bpl4 + s1];

    o4[ib4 + 0 * NP4 + d0] = i0a;
    o4[ib4 + 1 * NP4 + d0] = i1a;
    o4[ib4 + 2 * NP4 + d0] = i2a;
    o4[ib4 + 0 * NP4 + d1] = i0b;
    o4[ib4 + 1 * NP4 + d1] = i1b;
    o4[ib4 + 2 * NP4 + d1] = i2b;
    o4[LB4 + bpl4 + d0] = make_float4((float)lva.x, (float)lva.y,
                                      (float)lva.z, (float)lva.w);
    o4[LB4 + bpl4 + d1] = make_float4((float)lvb.x, (float)lvb.y,
                                      (float)lvb.z, (float)lvb.w);
    o4[CB4 + bpl4 + d0] = cva;
    o4[CB4 + bpl4 + d1] = cvb;
}

extern "C" void kernel_launch(void* const* d_in, const int* in_sizes, int n_in,
                              void* d_out, int out_size) {
    const float* oimage = (const float*)d_in[0];
    const float* aimage = (const float*)d_in[1];
    const int*   olabel = (const int*)  d_in[2];
    const int*   alabel = (const int*)  d_in[3];
    const float* oconf  = (const float*)d_in[4];
    const float* aconf  = (const float*)d_in[5];
    const float* pred   = (const float*)d_in[6];
    float* out = (float*)d_out;

    k_stage1<<<Bn * NSEG + 1024, 256>>>(pred, olabel, oconf, aconf);
    k_map<<<Bn, Pn>>>();
    k_scatter<<<Bn * 32, 256>>>(oimage, aimage, olabel, alabel,
                                oconf, aconf, out);
}

// round 6
// speedup vs baseline: 1.0770x; 1.0770x over previous
#include <cuda_runtime.h>

// ---------------------------------------------------------------------------
// AdaMix: self-paced patch mixing — 3-kernel version (R6).
//   K1: dice partials, 32 segments/sample, 10 front-batched loads per thread,
//       launch_bounds(256,4) so ptxas has ~64 regs (NO spill — R5's bug).
//       + per-patch conf means, float4-vectorized.
//   K2 (tiny): per-sample reduce -> k/sign -> stable ranks -> g_map.
//   K3: lean gather/scatter, 2 rows per thread, no smem, no syncs.
// ---------------------------------------------------------------------------

#define Bn    64
#define Cn    3
#define IMGn  256
#define NCn   4
#define Hn    32
#define Pn    64
#define TOPKn 16
#define NPIX  (IMGn * IMGn)   // 65536
#define NP4   (NPIX >> 2)     // 16384 float4 per plane
#define NSEG  32              // dice segments per sample

// scratch (allocation-free: __device__ globals)
// layout per (b,seg): [0:4)=inter, [4:8)=ssum, [8:12)=cnt
__device__ double g_part[Bn][NSEG][12];
__device__ float  g_omean[Bn][Pn];
__device__ float  g_amean[Bn][Pn];
__device__ int    g_map[Bn][Pn];   // bit8 = use-augmented, low 8 bits = src patch

// --- K1: dice partials (blocks 0..2047) + patch means (blocks 2048..3071) ---
__global__ void __launch_bounds__(256, 4)   // allow ~64 regs: no spill
k_stage1(const float* __restrict__ pred,
         const int*   __restrict__ olabel,
         const float* __restrict__ oconf,
         const float* __restrict__ aconf) {
    const int blk = blockIdx.x;
    const int t   = threadIdx.x;

    if (blk < Bn * NSEG) {
        // ---- dice partial sums: b = blk>>5, segment = blk&31 (2048 pixels)
        const int b   = blk >> 5;
        const int seg = blk & (NSEG - 1);
        const float4* p4 = (const float4*)(pred + (size_t)b * NCn * NPIX);
        const int4*   l4 = (const int4*)(olabel + (size_t)b * NPIX);
        const int i4a = seg * 512 + t;         // two float4 groups per thread
        const int i4b = i4a + 256;

        // front-batch all 10 loads (MLP = 10)
        float4 a0 = p4[i4a];
        float4 a1 = p4[i4a + NP4];
        float4 a2 = p4[i4a + 2 * NP4];
        float4 a3 = p4[i4a + 3 * NP4];
        int4   lA = l4[i4a];
        float4 b0 = p4[i4b];
        float4 b1 = p4[i4b + NP4];
        float4 b2 = p4[i4b + 2 * NP4];
        float4 b3 = p4[i4b + 3 * NP4];
        int4   lB = l4[i4b];

        float ssum[NCn]  = {0, 0, 0, 0};
        float inter[NCn] = {0, 0, 0, 0};
        float cnt[NCn]   = {0, 0, 0, 0};

        #pragma unroll
        for (int g = 0; g < 2; g++) {
            float x0[4], x1[4], x2[4], x3[4];
            int   lv[4];
            if (g == 0) {
                x0[0]=a0.x; x0[1]=a0.y; x0[2]=a0.z; x0[3]=a0.w;
                x1[0]=a1.x; x1[1]=a1.y; x1[2]=a1.z; x1[3]=a1.w;
                x2[0]=a2.x; x2[1]=a2.y; x2[2]=a2.z; x2[3]=a2.w;
                x3[0]=a3.x; x3[1]=a3.y; x3[2]=a3.z; x3[3]=a3.w;
                lv[0]=lA.x; lv[1]=lA.y; lv[2]=lA.z; lv[3]=lA.w;
            } else {
                x0[0]=b0.x; x0[1]=b0.y; x0[2]=b0.z; x0[3]=b0.w;
                x1[0]=b1.x; x1[1]=b1.y; x1[2]=b1.z; x1[3]=b1.w;
                x2[0]=b2.x; x2[1]=b2.y; x2[2]=b2.z; x2[3]=b2.w;
                x3[0]=b3.x; x3[1]=b3.y; x3[2]=b3.z; x3[3]=b3.w;
                lv[0]=lB.x; lv[1]=lB.y; lv[2]=lB.z; lv[3]=lB.w;
            }
            #pragma unroll
            for (int j = 0; j < 4; j++) {
                // inputs ~N(0,1): exp without max-shift is safe in fp32
                float e0 = __expf(x0[j]), e1 = __expf(x1[j]);
                float e2 = __expf(x2[j]), e3 = __expf(x3[j]);
                float inv = __frcp_rn((e0 + e1) + (e2 + e3));
                float s[NCn] = {e0 * inv, e1 * inv, e2 * inv, e3 * inv};
                const int lab = lv[j];
                #pragma unroll
                for (int c = 0; c < NCn; c++) {
                    float f = (lab == c) ? 1.0f : 0.0f;
                    ssum[c]  += s[c];
                    inter[c] = fmaf(f, s[c], inter[c]);
                    cnt[c]   += f;
                }
            }
        }

        // deterministic reduce: warp (double) -> shared -> thread 0
        __shared__ double sw[8][12];
        const int lane = t & 31, wid = t >> 5;
        #pragma unroll
        for (int c = 0; c < NCn; c++) {
            double vi = (double)inter[c];
            double vs = (double)ssum[c];
            double vc = (double)cnt[c];
            #pragma unroll
            for (int o = 16; o > 0; o >>= 1) {
                vi += __shfl_down_sync(0xffffffffu, vi, o);
                vs += __shfl_down_sync(0xffffffffu, vs, o);
                vc += __shfl_down_sync(0xffffffffu, vc, o);
            }
            if (lane == 0) { sw[wid][c] = vi; sw[wid][4 + c] = vs; sw[wid][8 + c] = vc; }
        }
        __syncthreads();
        if (t < 12) {
            double v = 0.0;
            #pragma unroll
            for (int w = 0; w < 8; w++) v += sw[w][t];
            g_part[b][seg][t] = v;
        }
    } else {
        // ---- patch means: m in [0,1024): b = m>>4, src = (m>>3)&1, band = m&7
        const int m    = blk - Bn * NSEG;
        const int b    = m >> 4;
        const int s    = (m >> 3) & 1;
        const int band = m & 7;
        const float4* src = (const float4*)((s ? aconf : oconf)
                              + (size_t)b * NPIX + band * Hn * IMGn);
        float acc = 0.0f;
        #pragma unroll
        for (int it = 0; it < 8; it++) {
            float4 v = src[it * 256 + t];
            acc += (v.x + v.y) + (v.z + v.w);
        }
        __shared__ float sacc[256];
        sacc[t] = acc;
        __syncthreads();
        if (t < 8) {
            float tot = 0.0f;
            #pragma unroll
            for (int g = 0; g < 4; g++)
                #pragma unroll
                for (int j = 0; j < 8; j++)
                    tot += sacc[g * 64 + t * 8 + j];
            float mean = tot * (1.0f / (Hn * Hn));
            if (s) g_amean[b][band * 8 + t] = mean;
            else   g_omean[b][band * 8 + t] = mean;
        }
    }
}

// --- K2 (tiny): per-sample loss -> k/sign -> stable ranks -> g_map ---------
__global__ void k_map() {
    const int b = blockIdx.x;
    const int t = threadIdx.x;   // 64 threads

    __shared__ double s12[12];
    __shared__ float  s_ko[Pn], s_ka[Pn];
    __shared__ int    s_oidx[Pn], s_aidx[Pn];
    __shared__ int    s_k;
    __shared__ float  s_sign;

    if (t < 12) {
        double v = 0.0;
        #pragma unroll
        for (int s = 0; s < NSEG; s++) v += g_part[b][s][t];
        s12[t] = v;
    }
    __syncthreads();
    if (t == 0) {
        double dice = 0.0;
        #pragma unroll
        for (int c = 0; c < NCn; c++) {
            double un = s12[4 + c] + s12[8 + c];
            dice += 2.0 * s12[c] / (un + 1e-5);
        }
        float lossf = (float)(1.0 - dice * 0.25);
        bool  mask  = lossf < 1.0f;                       // AGE = 1.0
        float spw   = 1.0f - lossf / (1.0f + 1e-5f);
        s_k    = min(TOPKn, (int)fabsf(truncf((float)TOPKn * spw)));
        s_sign = mask ? -1.0f : 1.0f;
    }
    __syncthreads();

    s_ko[t] =  s_sign * g_omean[b][t];
    s_ka[t] = -s_sign * g_amean[b][t];
    __syncthreads();

    float mo = s_ko[t], ma = s_ka[t];
    int ro = 0, ra = 0;
    #pragma unroll
    for (int q = 0; q < Pn; q++) {
        float vo = s_ko[q]; ro += (vo < mo) || (vo == mo && q < t);
        float va = s_ka[q]; ra += (va < ma) || (va == ma && q < t);
    }
    s_oidx[ro] = t;
    s_aidx[ra] = t;
    __syncthreads();

    int dest = s_oidx[t];
    g_map[b][dest] = (t < s_k) ? (s_aidx[t] | 256) : dest;
}

// --- K3: lean gather/scatter. Block = (b, 8-row band); thread does 2 rows. --
__global__ void k_scatter(const float* __restrict__ oimg,
                          const float* __restrict__ aimg,
                          const int*   __restrict__ olab,
                          const int*   __restrict__ alab,
                          const float* __restrict__ oconf,
                          const float* __restrict__ aconf,
                          float* __restrict__ out) {
    const int t    = threadIdx.x;
    const int b    = blockIdx.x >> 5;
    const int band = blockIdx.x & 31;       // 8 dest rows: band*8 .. band*8+7

    const int r  = t >> 6;                  // 0..3
    const int c4 = t & 63;
    const int x  = c4 << 2;
    const int y0 = (band << 3) + r;         // rows y0 and y0+4, same patch row
    const int p  = ((y0 >> 5) << 3) | (x >> 5);

    const int v    = __ldg(&g_map[b][p]);
    const int q    = v & 255;
    const bool sel = (v & 256) != 0;
    const int sy0 = ((q >> 3) << 5) | (y0 & 31);
    const int sx  = ((q & 7)  << 5) | (x & 31);

    const size_t d0 = (size_t)y0 * 64 + c4;              // within plane (float4)
    const size_t d1 = d0 + 4 * 64;
    const size_t s0 = ((size_t)sy0 * IMGn + sx) >> 2;
    const size_t s1 = s0 + 4 * 64;
    const size_t bpl4 = (size_t)b * NP4;

    const float4* img4 = (const float4*)(sel ? aimg : oimg);
    const int4*   lab4 = (const int4*)  (sel ? alab : olab);
    const float4* cnf4 = (const float4*)(sel ? aconf : oconf);
    float4* o4 = (float4*)out;

    const size_t ib4 = (size_t)b * Cn * NP4;
    const size_t LB4 = (size_t)Bn * Cn * NP4;        // label plane base (float4)
    const size_t CB4 = LB4 + (size_t)Bn * NP4;       // conf plane base

    // issue all 10 loads first (max MLP), then all 10 stores
    float4 i0a = img4[ib4 + 0 * NP4 + s0];
    float4 i1a = img4[ib4 + 1 * NP4 + s0];
    float4 i2a = img4[ib4 + 2 * NP4 + s0];
    float4 i0b = img4[ib4 + 0 * NP4 + s1];
    float4 i1b = img4[ib4 + 1 * NP4 + s1];
    float4 i2b = img4[ib4 + 2 * NP4 + s1];
    int4   lva = lab4[bpl4 + s0];
    int4   lvb = lab4[bpl4 + s1];
    float4 cva = cnf4[bpl4 + s0];
    float4 cvb = cnf4[bpl4 + s1];

    o4[ib4 + 0 * NP4 + d0] = i0a;
    o4[ib4 + 1 * NP4 + d0] = i1a;
    o4[ib4 + 2 * NP4 + d0] = i2a;
    o4[ib4 + 0 * NP4 + d1] = i0b;
    o4[ib4 + 1 * NP4 + d1] = i1b;
    o4[ib4 + 2 * NP4 + d1] = i2b;
    o4[LB4 + bpl4 + d0] = make_float4((float)lva.x, (float)lva.y,
                                      (float)lva.z, (float)lva.w);
    o4[LB4 + bpl4 + d1] = make_float4((float)lvb.x, (float)lvb.y,
                                      (float)lvb.z, (float)lvb.w);
    o4[CB4 + bpl4 + d0] = cva;
    o4[CB4 + bpl4 + d1] = cvb;
}

extern "C" void kernel_launch(void* const* d_in, const int* in_sizes, int n_in,
                              void* d_out, int out_size) {
    const float* oimage = (const float*)d_in[0];
    const float* aimage = (const float*)d_in[1];
    const int*   olabel = (const int*)  d_in[2];
    const int*   alabel = (const int*)  d_in[3];
    const float* oconf  = (const float*)d_in[4];
    const float* aconf  = (const float*)d_in[5];
    const float* pred   = (const float*)d_in[6];
    float* out = (float*)d_out;

    k_stage1<<<Bn * NSEG + 1024, 256>>>(pred, olabel, oconf, aconf);
    k_map<<<Bn, Pn>>>();
    k_scatter<<<Bn * 32, 256>>>(oimage, aimage, olabel, alabel,
                                oconf, aconf, out);
}

// round 7
// speedup vs baseline: 2.0893x; 1.9399x over previous
#include <cuda_runtime.h>

// ---------------------------------------------------------------------------
// AdaMix: self-paced patch mixing — 3-kernel version (R7).
//   Key insight from R4/R6: the per-block reduction epilogue (12 x double
//   shuffle trees) dominated stage1, not loads. Now: 8 fused quantities
//   (inter, union) reduced via float shared-memory + one warp each.
//   K1: dice partials (8 segments/sample, 512 blocks, MLP-10 load batches)
//       + per-patch conf means.
//   K2 (tiny): per-sample reduce -> k/sign -> stable ranks -> g_map.
//   K3: lean gather/scatter, 2 rows per thread, no smem, no syncs.
// ---------------------------------------------------------------------------

#define Bn    64
#define Cn    3
#define IMGn  256
#define NCn   4
#define Hn    32
#define Pn    64
#define TOPKn 16
#define NPIX  (IMGn * IMGn)   // 65536
#define NP4   (NPIX >> 2)     // 16384 float4 per plane
#define NSEG  8               // dice segments per sample

// scratch (allocation-free: __device__ globals)
// per (b,seg): [0:4)=inter, [4:8)=union
__device__ double g_part[Bn][NSEG][8];
__device__ float  g_omean[Bn][Pn];
__device__ float  g_amean[Bn][Pn];
__device__ int    g_map[Bn][Pn];   // bit8 = use-augmented, low 8 bits = src patch

// --- K1: dice partials (blocks 0..511) + patch means (blocks 512..1535) ----
__global__ void k_stage1(const float* __restrict__ pred,
                         const int*   __restrict__ olabel,
                         const float* __restrict__ oconf,
                         const float* __restrict__ aconf) {
    const int blk = blockIdx.x;
    const int t   = threadIdx.x;

    if (blk < Bn * NSEG) {
        // ---- dice partials: b = blk>>3, segment = blk&7 (8192 pixels)
        const int b   = blk >> 3;
        const int seg = blk & (NSEG - 1);
        const float4* p4 = (const float4*)(pred + (size_t)b * NCn * NPIX);
        const int4*   l4 = (const int4*)(olabel + (size_t)b * NPIX);
        const int base4 = seg * 2048;   // 2048 float4 per segment

        float inter[NCn] = {0, 0, 0, 0};
        float uni[NCn]   = {0, 0, 0, 0};

        #pragma unroll
        for (int it = 0; it < 4; it++) {
            const int i4a = base4 + it * 512 + t;
            const int i4b = i4a + 256;
            // front-batch 10 loads (MLP = 10)
            float4 a0 = p4[i4a];
            float4 a1 = p4[i4a + NP4];
            float4 a2 = p4[i4a + 2 * NP4];
            float4 a3 = p4[i4a + 3 * NP4];
            int4   lA = l4[i4a];
            float4 b0 = p4[i4b];
            float4 b1 = p4[i4b + NP4];
            float4 b2 = p4[i4b + 2 * NP4];
            float4 b3 = p4[i4b + 3 * NP4];
            int4   lB = l4[i4b];

            #pragma unroll
            for (int g = 0; g < 2; g++) {
                float x0[4], x1[4], x2[4], x3[4];
                int   lv[4];
                if (g == 0) {
                    x0[0]=a0.x; x0[1]=a0.y; x0[2]=a0.z; x0[3]=a0.w;
                    x1[0]=a1.x; x1[1]=a1.y; x1[2]=a1.z; x1[3]=a1.w;
                    x2[0]=a2.x; x2[1]=a2.y; x2[2]=a2.z; x2[3]=a2.w;
                    x3[0]=a3.x; x3[1]=a3.y; x3[2]=a3.z; x3[3]=a3.w;
                    lv[0]=lA.x; lv[1]=lA.y; lv[2]=lA.z; lv[3]=lA.w;
                } else {
                    x0[0]=b0.x; x0[1]=b0.y; x0[2]=b0.z; x0[3]=b0.w;
                    x1[0]=b1.x; x1[1]=b1.y; x1[2]=b1.z; x1[3]=b1.w;
                    x2[0]=b2.x; x2[1]=b2.y; x2[2]=b2.z; x2[3]=b2.w;
                    x3[0]=b3.x; x3[1]=b3.y; x3[2]=b3.z; x3[3]=b3.w;
                    lv[0]=lB.x; lv[1]=lB.y; lv[2]=lB.z; lv[3]=lB.w;
                }
                #pragma unroll
                for (int j = 0; j < 4; j++) {
                    // inputs ~N(0,1): exp without max-shift is safe in fp32
                    float e0 = __expf(x0[j]), e1 = __expf(x1[j]);
                    float e2 = __expf(x2[j]), e3 = __expf(x3[j]);
                    float inv = __frcp_rn((e0 + e1) + (e2 + e3));
                    float s[NCn] = {e0 * inv, e1 * inv, e2 * inv, e3 * inv};
                    const int lab = lv[j];
                    #pragma unroll
                    for (int c = 0; c < NCn; c++) {
                        float f = (lab == c) ? 1.0f : 0.0f;
                        inter[c] = fmaf(f, s[c], inter[c]);
                        uni[c]  += s[c] + f;       // softmax-sum + one-hot count
                    }
                }
            }
        }

        // cheap epilogue: float shared reduce, one warp per quantity
        __shared__ float sred[8][256];
        #pragma unroll
        for (int q = 0; q < NCn; q++) {
            sred[q][t]       = inter[q];
            sred[4 + q][t]   = uni[q];
        }
        __syncthreads();
        const int w = t >> 5, lane = t & 31;
        float v = sred[w][lane];
        #pragma unroll
        for (int j = 1; j < 8; j++) v += sred[w][lane + 32 * j];
        #pragma unroll
        for (int o = 16; o > 0; o >>= 1) v += __shfl_down_sync(0xffffffffu, v, o);
        if (lane == 0) g_part[b][seg][w] = (double)v;
    } else {
        // ---- patch means: m in [0,1024): b = m>>4, src = (m>>3)&1, band = m&7
        const int m    = blk - Bn * NSEG;
        const int b    = m >> 4;
        const int s    = (m >> 3) & 1;
        const int band = m & 7;
        const float4* src = (const float4*)((s ? aconf : oconf)
                              + (size_t)b * NPIX + band * Hn * IMGn);
        float acc = 0.0f;
        #pragma unroll
        for (int it = 0; it < 8; it++) {
            float4 v = src[it * 256 + t];
            acc += (v.x + v.y) + (v.z + v.w);
        }
        __shared__ float sacc[256];
        sacc[t] = acc;
        __syncthreads();
        if (t < 8) {
            float tot = 0.0f;
            #pragma unroll
            for (int g = 0; g < 4; g++)
                #pragma unroll
                for (int j = 0; j < 8; j++)
                    tot += sacc[g * 64 + t * 8 + j];
            float mean = tot * (1.0f / (Hn * Hn));
            if (s) g_amean[b][band * 8 + t] = mean;
            else   g_omean[b][band * 8 + t] = mean;
        }
    }
}

// --- K2 (tiny): per-sample loss -> k/sign -> stable ranks -> g_map ---------
__global__ void k_map() {
    const int b = blockIdx.x;
    const int t = threadIdx.x;   // 64 threads

    __shared__ double s8[8];
    __shared__ float  s_ko[Pn], s_ka[Pn];
    __shared__ int    s_oidx[Pn], s_aidx[Pn];
    __shared__ int    s_k;
    __shared__ float  s_sign;

    if (t < 8) {
        double v = 0.0;
        #pragma unroll
        for (int s = 0; s < NSEG; s++) v += g_part[b][s][t];
        s8[t] = v;
    }
    __syncthreads();
    if (t == 0) {
        double dice = 0.0;
        #pragma unroll
        for (int c = 0; c < NCn; c++)
            dice += 2.0 * s8[c] / (s8[4 + c] + 1e-5);
        float lossf = (float)(1.0 - dice * 0.25);
        bool  mask  = lossf < 1.0f;                       // AGE = 1.0
        float spw   = 1.0f - lossf / (1.0f + 1e-5f);
        s_k    = min(TOPKn, (int)fabsf(truncf((float)TOPKn * spw)));
        s_sign = mask ? -1.0f : 1.0f;
    }
    __syncthreads();

    s_ko[t] =  s_sign * g_omean[b][t];
    s_ka[t] = -s_sign * g_amean[b][t];
    __syncthreads();

    float mo = s_ko[t], ma = s_ka[t];
    int ro = 0, ra = 0;
    #pragma unroll
    for (int q = 0; q < Pn; q++) {
        float vo = s_ko[q]; ro += (vo < mo) || (vo == mo && q < t);
        float va = s_ka[q]; ra += (va < ma) || (va == ma && q < t);
    }
    s_oidx[ro] = t;
    s_aidx[ra] = t;
    __syncthreads();

    int dest = s_oidx[t];
    g_map[b][dest] = (t < s_k) ? (s_aidx[t] | 256) : dest;
}

// --- K3: lean gather/scatter. Block = (b, 8-row band); thread does 2 rows. --
__global__ void k_scatter(const float* __restrict__ oimg,
                          const float* __restrict__ aimg,
                          const int*   __restrict__ olab,
                          const int*   __restrict__ alab,
                          const float* __restrict__ oconf,
                          const float* __restrict__ aconf,
                          float* __restrict__ out) {
    const int t    = threadIdx.x;
    const int b    = blockIdx.x >> 5;
    const int band = blockIdx.x & 31;       // 8 dest rows: band*8 .. band*8+7

    const int r  = t >> 6;                  // 0..3
    const int c4 = t & 63;
    const int x  = c4 << 2;
    const int y0 = (band << 3) + r;         // rows y0 and y0+4, same patch row
    const int p  = ((y0 >> 5) << 3) | (x >> 5);

    const int v    = __ldg(&g_map[b][p]);
    const int q    = v & 255;
    const bool sel = (v & 256) != 0;
    const int sy0 = ((q >> 3) << 5) | (y0 & 31);
    const int sx  = ((q & 7)  << 5) | (x & 31);

    const size_t d0 = (size_t)y0 * 64 + c4;              // within plane (float4)
    const size_t d1 = d0 + 4 * 64;
    const size_t s0 = ((size_t)sy0 * IMGn + sx) >> 2;
    const size_t s1 = s0 + 4 * 64;
    const size_t bpl4 = (size_t)b * NP4;

    const float4* img4 = (const float4*)(sel ? aimg : oimg);
    const int4*   lab4 = (const int4*)  (sel ? alab : olab);
    const float4* cnf4 = (const float4*)(sel ? aconf : oconf);
    float4* o4 = (float4*)out;

    const size_t ib4 = (size_t)b * Cn * NP4;
    const size_t LB4 = (size_t)Bn * Cn * NP4;        // label plane base (float4)
    const size_t CB4 = LB4 + (size_t)Bn * NP4;       // conf plane base

    // issue all 10 loads first (max MLP), then all 10 stores
    float4 i0a = img4[ib4 + 0 * NP4 + s0];
    float4 i1a = img4[ib4 + 1 * NP4 + s0];
    float4 i2a = img4[ib4 + 2 * NP4 + s0];
    float4 i0b = img4[ib4 + 0 * NP4 + s1];
    float4 i1b = img4[ib4 + 1 * NP4 + s1];
    float4 i2b = img4[ib4 + 2 * NP4 + s1];
    int4   lva = lab4[bpl4 + s0];
    int4   lvb = lab4[bpl4 + s1];
    float4 cva = cnf4[bpl4 + s0];
    float4 cvb = cnf4[bpl4 + s1];

    o4[ib4 + 0 * NP4 + d0] = i0a;
    o4[ib4 + 1 * NP4 + d0] = i1a;
    o4[ib4 + 2 * NP4 + d0] = i2a;
    o4[ib4 + 0 * NP4 + d1] = i0b;
    o4[ib4 + 1 * NP4 + d1] = i1b;
    o4[ib4 + 2 * NP4 + d1] = i2b;
    o4[LB4 + bpl4 + d0] = make_float4((float)lva.x, (float)lva.y,
                                      (float)lva.z, (float)lva.w);
    o4[LB4 + bpl4 + d1] = make_float4((float)lvb.x, (float)lvb.y,
                                      (float)lvb.z, (float)lvb.w);
    o4[CB4 + bpl4 + d0] = cva;
    o4[CB4 + bpl4 + d1] = cvb;
}

extern "C" void kernel_launch(void* const* d_in, const int* in_sizes, int n_in,
                              void* d_out, int out_size) {
    const float* oimage = (const float*)d_in[0];
    const float* aimage = (const float*)d_in[1];
    const int*   olabel = (const int*)  d_in[2];
    const int*   alabel = (const int*)  d_in[3];
    const float* oconf  = (const float*)d_in[4];
    const float* aconf  = (const float*)d_in[5];
    const float* pred   = (const float*)d_in[6];
    float* out = (float*)d_out;

    k_stage1<<<Bn * NSEG + 1024, 256>>>(pred, olabel, oconf, aconf);
    k_map<<<Bn, Pn>>>();
    k_scatter<<<Bn * 32, 256>>>(oimage, aimage, olabel, alabel,
                                oconf, aconf, out);
}

// round 8
// speedup vs baseline: 2.1919x; 1.0491x over previous
#include <cuda_runtime.h>

// ---------------------------------------------------------------------------
// AdaMix: self-paced patch mixing — 2-kernel version (R8).
//   K1: dice partials (8 seg/sample) + per-patch conf means, and a fused
//       per-sample map: the 24th (last) block contributing to sample b
//       computes loss->k, rank-sorts, writes g_map[b] in-kernel.
//       launch_bounds(256,4) -> 64 regs, 4 CTA/SM (R6 proved no spill).
//   K2: lean gather/scatter, 2 rows per thread, no smem, no syncs.
// ---------------------------------------------------------------------------

#define Bn    64
#define Cn    3
#define IMGn  256
#define NCn   4
#define Hn    32
#define Pn    64
#define TOPKn 16
#define NPIX  (IMGn * IMGn)   // 65536
#define NP4   (NPIX >> 2)     // 16384 float4 per plane
#define NSEG  8               // dice segments per sample
#define ARRIVALS (NSEG + 16)  // blocks contributing to one sample

// scratch (allocation-free: __device__ globals)
__device__ double g_part[Bn][NSEG][8];   // [0:4)=inter, [4:8)=union
__device__ float  g_omean[Bn][Pn];
__device__ float  g_amean[Bn][Pn];
__device__ int    g_map[Bn][Pn];   // bit8 = use-augmented, low 8 = src patch
__device__ unsigned int g_done[Bn];      // zero-init; self-resetting

// per-sample map: run by all 256 threads of the winning block
__device__ __forceinline__ void do_map(int b, int t) {
    __shared__ double s8[8];
    __shared__ float  s_ko[Pn], s_ka[Pn];
    __shared__ int    s_oidx[Pn], s_aidx[Pn];
    __shared__ int    s_k;
    __shared__ float  s_sign;

    if (t < 8) {
        double v = 0.0;
        #pragma unroll
        for (int s = 0; s < NSEG; s++) v += g_part[b][s][t];
        s8[t] = v;
    }
    __syncthreads();
    if (t == 0) {
        double dice = 0.0;
        #pragma unroll
        for (int c = 0; c < NCn; c++)
            dice += 2.0 * s8[c] / (s8[4 + c] + 1e-5);
        float lossf = (float)(1.0 - dice * 0.25);
        bool  mask  = lossf < 1.0f;                       // AGE = 1.0
        float spw   = 1.0f - lossf / (1.0f + 1e-5f);
        s_k    = min(TOPKn, (int)fabsf(truncf((float)TOPKn * spw)));
        s_sign = mask ? -1.0f : 1.0f;
    }
    __syncthreads();
    if (t < Pn) {
        s_ko[t] =  s_sign * g_omean[b][t];
        s_ka[t] = -s_sign * g_amean[b][t];
    }
    __syncthreads();
    if (t < Pn) {
        float mo = s_ko[t], ma = s_ka[t];
        int ro = 0, ra = 0;
        #pragma unroll
        for (int q = 0; q < Pn; q++) {
            float vo = s_ko[q]; ro += (vo < mo) || (vo == mo && q < t);
            float va = s_ka[q]; ra += (va < ma) || (va == ma && q < t);
        }
        s_oidx[ro] = t;
        s_aidx[ra] = t;
    }
    __syncthreads();
    if (t < Pn) {
        int dest = s_oidx[t];
        g_map[b][dest] = (t < s_k) ? (s_aidx[t] | 256) : dest;
    }
    if (t == 0) g_done[b] = 0;   // reset for next graph replay
}

// --- K1: dice partials (blocks 0..511) + patch means (blocks 512..1535) ----
__global__ void __launch_bounds__(256, 4)
k_stage1(const float* __restrict__ pred,
         const int*   __restrict__ olabel,
         const float* __restrict__ oconf,
         const float* __restrict__ aconf) {
    const int blk = blockIdx.x;
    const int t   = threadIdx.x;
    int b;   // sample this block contributes to

    if (blk < Bn * NSEG) {
        // ---- dice partials: b = blk>>3, segment = blk&7 (8192 pixels)
        b = blk >> 3;
        const int seg = blk & (NSEG - 1);
        const float4* p4 = (const float4*)(pred + (size_t)b * NCn * NPIX);
        const int4*   l4 = (const int4*)(olabel + (size_t)b * NPIX);
        const int base4 = seg * 2048;   // 2048 float4 per segment

        float inter[NCn] = {0, 0, 0, 0};
        float uni[NCn]   = {0, 0, 0, 0};

        #pragma unroll
        for (int it = 0; it < 4; it++) {
            const int i4a = base4 + it * 512 + t;
            const int i4b = i4a + 256;
            // front-batch 10 loads (MLP = 10)
            float4 a0 = p4[i4a];
            float4 a1 = p4[i4a + NP4];
            float4 a2 = p4[i4a + 2 * NP4];
            float4 a3 = p4[i4a + 3 * NP4];
            int4   lA = l4[i4a];
            float4 b0 = p4[i4b];
            float4 b1 = p4[i4b + NP4];
            float4 b2 = p4[i4b + 2 * NP4];
            float4 b3 = p4[i4b + 3 * NP4];
            int4   lB = l4[i4b];

            #pragma unroll
            for (int g = 0; g < 2; g++) {
                float x0[4], x1[4], x2[4], x3[4];
                int   lv[4];
                if (g == 0) {
                    x0[0]=a0.x; x0[1]=a0.y; x0[2]=a0.z; x0[3]=a0.w;
                    x1[0]=a1.x; x1[1]=a1.y; x1[2]=a1.z; x1[3]=a1.w;
                    x2[0]=a2.x; x2[1]=a2.y; x2[2]=a2.z; x2[3]=a2.w;
                    x3[0]=a3.x; x3[1]=a3.y; x3[2]=a3.z; x3[3]=a3.w;
                    lv[0]=lA.x; lv[1]=lA.y; lv[2]=lA.z; lv[3]=lA.w;
                } else {
                    x0[0]=b0.x; x0[1]=b0.y; x0[2]=b0.z; x0[3]=b0.w;
                    x1[0]=b1.x; x1[1]=b1.y; x1[2]=b1.z; x1[3]=b1.w;
                    x2[0]=b2.x; x2[1]=b2.y; x2[2]=b2.z; x2[3]=b2.w;
                    x3[0]=b3.x; x3[1]=b3.y; x3[2]=b3.z; x3[3]=b3.w;
                    lv[0]=lB.x; lv[1]=lB.y; lv[2]=lB.z; lv[3]=lB.w;
                }
                #pragma unroll
                for (int j = 0; j < 4; j++) {
                    // inputs ~N(0,1): exp without max-shift is safe in fp32
                    float e0 = __expf(x0[j]), e1 = __expf(x1[j]);
                    float e2 = __expf(x2[j]), e3 = __expf(x3[j]);
                    float inv = __frcp_rn((e0 + e1) + (e2 + e3));
                    float s[NCn] = {e0 * inv, e1 * inv, e2 * inv, e3 * inv};
                    const int lab = lv[j];
                    #pragma unroll
                    for (int c = 0; c < NCn; c++) {
                        float f = (lab == c) ? 1.0f : 0.0f;
                        inter[c] = fmaf(f, s[c], inter[c]);
                        uni[c]  += s[c] + f;   // softmax-sum + one-hot count
                    }
                }
            }
        }

        // cheap epilogue: float shared reduce, one warp per quantity
        __shared__ float sred[8][256];
        #pragma unroll
        for (int q = 0; q < NCn; q++) {
            sred[q][t]     = inter[q];
            sred[4 + q][t] = uni[q];
        }
        __syncthreads();
        const int w = t >> 5, lane = t & 31;
        float v = sred[w][lane];
        #pragma unroll
        for (int j = 1; j < 8; j++) v += sred[w][lane + 32 * j];
        #pragma unroll
        for (int o = 16; o > 0; o >>= 1) v += __shfl_down_sync(0xffffffffu, v, o);
        if (lane == 0) g_part[b][seg][w] = (double)v;
    } else {
        // ---- patch means: m in [0,1024): b = m>>4, src = (m>>3)&1, band = m&7
        const int m    = blk - Bn * NSEG;
        b = m >> 4;
        const int s    = (m >> 3) & 1;
        const int band = m & 7;
        const float4* src = (const float4*)((s ? aconf : oconf)
                              + (size_t)b * NPIX + band * Hn * IMGn);
        float acc = 0.0f;
        #pragma unroll
        for (int it = 0; it < 8; it++) {
            float4 v = src[it * 256 + t];
            acc += (v.x + v.y) + (v.z + v.w);
        }
        __shared__ float sacc[256];
        sacc[t] = acc;
        __syncthreads();
        if (t < 8) {
            float tot = 0.0f;
            #pragma unroll
            for (int g = 0; g < 4; g++)
                #pragma unroll
                for (int j = 0; j < 8; j++)
                    tot += sacc[g * 64 + t * 8 + j];
            float mean = tot * (1.0f / (Hn * Hn));
            if (s) g_amean[b][band * 8 + t] = mean;
            else   g_omean[b][band * 8 + t] = mean;
        }
    }

    // ---- arrival protocol: 24th block for sample b computes its map -------
    __syncthreads();          // all block writes done
    __threadfence();          // release this thread's global writes
    __shared__ int s_win;
    if (t == 0) {
        unsigned int old = atomicAdd(&g_done[b], 1u);
        s_win = (old == ARRIVALS - 1) ? 1 : 0;
    }
    __syncthreads();
    if (s_win) {
        __threadfence();      // acquire: see all 24 blocks' writes
        do_map(b, t);
    }
}

// --- K2: lean gather/scatter. Block = (b, 8-row band); thread does 2 rows. --
__global__ void k_scatter(const float* __restrict__ oimg,
                          const float* __restrict__ aimg,
                          const int*   __restrict__ olab,
                          const int*   __restrict__ alab,
                          const float* __restrict__ oconf,
                          const float* __restrict__ aconf,
                          float* __restrict__ out) {
    const int t    = threadIdx.x;
    const int b    = blockIdx.x >> 5;
    const int band = blockIdx.x & 31;       // 8 dest rows: band*8 .. band*8+7

    const int r  = t >> 6;                  // 0..3
    const int c4 = t & 63;
    const int x  = c4 << 2;
    const int y0 = (band << 3) + r;         // rows y0 and y0+4, same patch row
    const int p  = ((y0 >> 5) << 3) | (x >> 5);

    const int v    = __ldg(&g_map[b][p]);
    const int q    = v & 255;
    const bool sel = (v & 256) != 0;
    const int sy0 = ((q >> 3) << 5) | (y0 & 31);
    const int sx  = ((q & 7)  << 5) | (x & 31);

    const size_t d0 = (size_t)y0 * 64 + c4;              // within plane (float4)
    const size_t d1 = d0 + 4 * 64;
    const size_t s0 = ((size_t)sy0 * IMGn + sx) >> 2;
    const size_t s1 = s0 + 4 * 64;
    const size_t bpl4 = (size_t)b * NP4;

    const float4* img4 = (const float4*)(sel ? aimg : oimg);
    const int4*   lab4 = (const int4*)  (sel ? alab : olab);
    const float4* cnf4 = (const float4*)(sel ? aconf : oconf);
    float4* o4 = (float4*)out;

    const size_t ib4 = (size_t)b * Cn * NP4;
    const size_t LB4 = (size_t)Bn * Cn * NP4;        // label plane base (float4)
    const size_t CB4 = LB4 + (size_t)Bn * NP4;       // conf plane base

    // issue all 10 loads first (max MLP), then all 10 stores
    float4 i0a = img4[ib4 + 0 * NP4 + s0];
    float4 i1a = img4[ib4 + 1 * NP4 + s0];
    float4 i2a = img4[ib4 + 2 * NP4 + s0];
    float4 i0b = img4[ib4 + 0 * NP4 + s1];
    float4 i1b = img4[ib4 + 1 * NP4 + s1];
    float4 i2b = img4[ib4 + 2 * NP4 + s1];
    int4   lva = lab4[bpl4 + s0];
    int4   lvb = lab4[bpl4 + s1];
    float4 cva = cnf4[bpl4 + s0];
    float4 cvb = cnf4[bpl4 + s1];

    o4[ib4 + 0 * NP4 + d0] = i0a;
    o4[ib4 + 1 * NP4 + d0] = i1a;
    o4[ib4 + 2 * NP4 + d0] = i2a;
    o4[ib4 + 0 * NP4 + d1] = i0b;
    o4[ib4 + 1 * NP4 + d1] = i1b;
    o4[ib4 + 2 * NP4 + d1] = i2b;
    o4[LB4 + bpl4 + d0] = make_float4((float)lva.x, (float)lva.y,
                                      (float)lva.z, (float)lva.w);
    o4[LB4 + bpl4 + d1] = make_float4((float)lvb.x, (float)lvb.y,
                                      (float)lvb.z, (float)lvb.w);
    o4[CB4 + bpl4 + d0] = cva;
    o4[CB4 + bpl4 + d1] = cvb;
}

extern "C" void kernel_launch(void* const* d_in, const int* in_sizes, int n_in,
                              void* d_out, int out_size) {
    const float* oimage = (const float*)d_in[0];
    const float* aimage = (const float*)d_in[1];
    const int*   olabel = (const int*)  d_in[2];
    const int*   alabel = (const int*)  d_in[3];
    const float* oconf  = (const float*)d_in[4];
    const float* aconf  = (const float*)d_in[5];
    const float* pred   = (const float*)d_in[6];
    float* out = (float*)d_out;

    k_stage1<<<Bn * NSEG + 1024, 256>>>(pred, olabel, oconf, aconf);
    k_scatter<<<Bn * 32, 256>>>(oimage, aimage, olabel, alabel,
                                oconf, aconf, out);
}

// round 9
// speedup vs baseline: 2.3350x; 1.0653x over previous
#include <cuda_runtime.h>

// ---------------------------------------------------------------------------
// AdaMix: self-paced patch mixing — SINGLE fused kernel (R9).
//   blocks [0,512):     dice partials (8 seg/sample)
//   blocks [512,1536):  per-patch conf means
//     -> 24th arriving block per sample computes loss->k, rank-sort, g_map,
//        then releases g_ready[b].
//   blocks [1536,3584): gather/scatter; spin on g_ready[b], then copy.
//   All counters self-reset for graph replay. Producers (low block idx) never
//   wait => no deadlock under in-order dispatch.
// ---------------------------------------------------------------------------

#define Bn    64
#define Cn    3
#define IMGn  256
#define NCn   4
#define Hn    32
#define Pn    64
#define TOPKn 16
#define NPIX  (IMGn * IMGn)   // 65536
#define NP4   (NPIX >> 2)     // 16384 float4 per plane
#define NSEG  8               // dice segments per sample
#define ARRIVALS (NSEG + 16)  // stage1 blocks contributing to one sample
#define NB_S1 (Bn * NSEG + 1024)   // 1536
#define NB_SC (Bn * 32)            // 2048

// scratch (allocation-free: __device__ globals; zero-init, self-resetting)
__device__ double g_part[Bn][NSEG][8];   // [0:4)=inter, [4:8)=union
__device__ float  g_omean[Bn][Pn];
__device__ float  g_amean[Bn][Pn];
__device__ int    g_map[Bn][Pn];   // bit8 = use-augmented, low 8 = src patch
__device__ unsigned int g_done[Bn];      // stage1 arrivals
__device__ unsigned int g_ready[Bn];     // map published flag
__device__ unsigned int g_sdone[Bn];     // scatter arrivals (for reset)

// per-sample map: run by all 256 threads of the winning block
__device__ __forceinline__ void do_map(int b, int t) {
    __shared__ double s8[8];
    __shared__ float  s_ko[Pn], s_ka[Pn];
    __shared__ int    s_oidx[Pn], s_aidx[Pn];
    __shared__ int    s_k;
    __shared__ float  s_sign;

    if (t < 8) {
        double v = 0.0;
        #pragma unroll
        for (int s = 0; s < NSEG; s++) v += g_part[b][s][t];
        s8[t] = v;
    }
    __syncthreads();
    if (t == 0) {
        double dice = 0.0;
        #pragma unroll
        for (int c = 0; c < NCn; c++)
            dice += 2.0 * s8[c] / (s8[4 + c] + 1e-5);
        float lossf = (float)(1.0 - dice * 0.25);
        bool  mask  = lossf < 1.0f;                       // AGE = 1.0
        float spw   = 1.0f - lossf / (1.0f + 1e-5f);
        s_k    = min(TOPKn, (int)fabsf(truncf((float)TOPKn * spw)));
        s_sign = mask ? -1.0f : 1.0f;
    }
    __syncthreads();
    if (t < Pn) {
        s_ko[t] =  s_sign * g_omean[b][t];
        s_ka[t] = -s_sign * g_amean[b][t];
    }
    __syncthreads();
    if (t < Pn) {
        float mo = s_ko[t], ma = s_ka[t];
        int ro = 0, ra = 0;
        #pragma unroll
        for (int q = 0; q < Pn; q++) {
            float vo = s_ko[q]; ro += (vo < mo) || (vo == mo && q < t);
            float va = s_ka[q]; ra += (va < ma) || (va == ma && q < t);
        }
        s_oidx[ro] = t;
        s_aidx[ra] = t;
    }
    __syncthreads();
    if (t < Pn) {
        int dest = s_oidx[t];
        g_map[b][dest] = (t < s_k) ? (s_aidx[t] | 256) : dest;
    }
    __syncthreads();
    if (t == 0) {
        g_done[b] = 0;               // reset for next graph replay
        __threadfence();             // publish map before raising flag
        atomicExch(&g_ready[b], 1u);
    }
}

__global__ void k_fused(const float* __restrict__ pred,
                        const int*   __restrict__ olabel,
                        const float* __restrict__ oimg,
                        const float* __restrict__ aimg,
                        const int*   __restrict__ olab,
                        const int*   __restrict__ alab,
                        const float* __restrict__ oconf,
                        const float* __restrict__ aconf,
                        float* __restrict__ out) {
    const int blk = blockIdx.x;
    const int t   = threadIdx.x;

    if (blk < Bn * NSEG) {
        // ================= dice partials: b = blk>>3, seg = blk&7 ==========
        const int b   = blk >> 3;
        const int seg = blk & (NSEG - 1);
        const float4* p4 = (const float4*)(pred + (size_t)b * NCn * NPIX);
        const int4*   l4 = (const int4*)(olabel + (size_t)b * NPIX);
        const int base4 = seg * 2048;

        float inter[NCn] = {0, 0, 0, 0};
        float uni[NCn]   = {0, 0, 0, 0};

        #pragma unroll
        for (int it = 0; it < 4; it++) {
            const int i4a = base4 + it * 512 + t;
            const int i4b = i4a + 256;
            float4 a0 = p4[i4a];
            float4 a1 = p4[i4a + NP4];
            float4 a2 = p4[i4a + 2 * NP4];
            float4 a3 = p4[i4a + 3 * NP4];
            int4   lA = l4[i4a];
            float4 b0 = p4[i4b];
            float4 b1 = p4[i4b + NP4];
            float4 b2 = p4[i4b + 2 * NP4];
            float4 b3 = p4[i4b + 3 * NP4];
            int4   lB = l4[i4b];

            #pragma unroll
            for (int g = 0; g < 2; g++) {
                float x0[4], x1[4], x2[4], x3[4];
                int   lv[4];
                if (g == 0) {
                    x0[0]=a0.x; x0[1]=a0.y; x0[2]=a0.z; x0[3]=a0.w;
                    x1[0]=a1.x; x1[1]=a1.y; x1[2]=a1.z; x1[3]=a1.w;
                    x2[0]=a2.x; x2[1]=a2.y; x2[2]=a2.z; x2[3]=a2.w;
                    x3[0]=a3.x; x3[1]=a3.y; x3[2]=a3.z; x3[3]=a3.w;
                    lv[0]=lA.x; lv[1]=lA.y; lv[2]=lA.z; lv[3]=lA.w;
                } else {
                    x0[0]=b0.x; x0[1]=b0.y; x0[2]=b0.z; x0[3]=b0.w;
                    x1[0]=b1.x; x1[1]=b1.y; x1[2]=b1.z; x1[3]=b1.w;
                    x2[0]=b2.x; x2[1]=b2.y; x2[2]=b2.z; x2[3]=b2.w;
                    x3[0]=b3.x; x3[1]=b3.y; x3[2]=b3.z; x3[3]=b3.w;
                    lv[0]=lB.x; lv[1]=lB.y; lv[2]=lB.z; lv[3]=lB.w;
                }
                #pragma unroll
                for (int j = 0; j < 4; j++) {
                    float e0 = __expf(x0[j]), e1 = __expf(x1[j]);
                    float e2 = __expf(x2[j]), e3 = __expf(x3[j]);
                    float inv = __frcp_rn((e0 + e1) + (e2 + e3));
                    float s[NCn] = {e0 * inv, e1 * inv, e2 * inv, e3 * inv};
                    const int lab = lv[j];
                    #pragma unroll
                    for (int c = 0; c < NCn; c++) {
                        float f = (lab == c) ? 1.0f : 0.0f;
                        inter[c] = fmaf(f, s[c], inter[c]);
                        uni[c]  += s[c] + f;
                    }
                }
            }
        }

        __shared__ float sred[8][256];
        #pragma unroll
        for (int q = 0; q < NCn; q++) {
            sred[q][t]     = inter[q];
            sred[4 + q][t] = uni[q];
        }
        __syncthreads();
        const int w = t >> 5, lane = t & 31;
        float v = sred[w][lane];
        #pragma unroll
        for (int j = 1; j < 8; j++) v += sred[w][lane + 32 * j];
        #pragma unroll
        for (int o = 16; o > 0; o >>= 1) v += __shfl_down_sync(0xffffffffu, v, o);
        if (lane == 0) g_part[b][seg][w] = (double)v;

        // arrival
        __syncthreads();
        __threadfence();
        __shared__ int s_win;
        if (t == 0)
            s_win = (atomicAdd(&g_done[b], 1u) == ARRIVALS - 1) ? 1 : 0;
        __syncthreads();
        if (s_win) { __threadfence(); do_map(b, t); }

    } else if (blk < NB_S1) {
        // ================= patch means ======================================
        const int m    = blk - Bn * NSEG;
        const int b    = m >> 4;
        const int s    = (m >> 3) & 1;
        const int band = m & 7;
        const float4* src = (const float4*)((s ? aconf : oconf)
                              + (size_t)b * NPIX + band * Hn * IMGn);
        float acc = 0.0f;
        #pragma unroll
        for (int it = 0; it < 8; it++) {
            float4 v = src[it * 256 + t];
            acc += (v.x + v.y) + (v.z + v.w);
        }
        __shared__ float sacc[256];
        sacc[t] = acc;
        __syncthreads();
        if (t < 8) {
            float tot = 0.0f;
            #pragma unroll
            for (int g = 0; g < 4; g++)
                #pragma unroll
                for (int j = 0; j < 8; j++)
                    tot += sacc[g * 64 + t * 8 + j];
            float mean = tot * (1.0f / (Hn * Hn));
            if (s) g_amean[b][band * 8 + t] = mean;
            else   g_omean[b][band * 8 + t] = mean;
        }

        // arrival
        __syncthreads();
        __threadfence();
        __shared__ int s_win;
        if (t == 0)
            s_win = (atomicAdd(&g_done[b], 1u) == ARRIVALS - 1) ? 1 : 0;
        __syncthreads();
        if (s_win) { __threadfence(); do_map(b, t); }

    } else {
        // ================= scatter: wait for map, then copy =================
        const int m    = blk - NB_S1;
        const int b    = m >> 5;
        const int band = m & 31;

        if (t == 0) {
            while (atomicAdd(&g_ready[b], 0u) == 0u) __nanosleep(64);
        }
        __syncthreads();
        __threadfence();   // acquire: map visible

        const int r  = t >> 6;
        const int c4 = t & 63;
        const int x  = c4 << 2;
        const int y0 = (band << 3) + r;
        const int p  = ((y0 >> 5) << 3) | (x >> 5);

        const int v    = *(volatile int*)&g_map[b][p];   // bypass L1
        const int q    = v & 255;
        const bool sel = (v & 256) != 0;
        const int sy0 = ((q >> 3) << 5) | (y0 & 31);
        const int sx  = ((q & 7)  << 5) | (x & 31);

        const size_t d0 = (size_t)y0 * 64 + c4;
        const size_t d1 = d0 + 4 * 64;
        const size_t s0 = ((size_t)sy0 * IMGn + sx) >> 2;
        const size_t s1 = s0 + 4 * 64;
        const size_t bpl4 = (size_t)b * NP4;

        const float4* img4 = (const float4*)(sel ? aimg : oimg);
        const int4*   lab4 = (const int4*)  (sel ? alab : olab);
        const float4* cnf4 = (const float4*)(sel ? aconf : oconf);
        float4* o4 = (float4*)out;

        const size_t ib4 = (size_t)b * Cn * NP4;
        const size_t LB4 = (size_t)Bn * Cn * NP4;
        const size_t CB4 = LB4 + (size_t)Bn * NP4;

        float4 i0a = img4[ib4 + 0 * NP4 + s0];
        float4 i1a = img4[ib4 + 1 * NP4 + s0];
        float4 i2a = img4[ib4 + 2 * NP4 + s0];
        float4 i0b = img4[ib4 + 0 * NP4 + s1];
        float4 i1b = img4[ib4 + 1 * NP4 + s1];
        float4 i2b = img4[ib4 + 2 * NP4 + s1];
        int4   lva = lab4[bpl4 + s0];
        int4   lvb = lab4[bpl4 + s1];
        float4 cva = cnf4[bpl4 + s0];
        float4 cvb = cnf4[bpl4 + s1];

        o4[ib4 + 0 * NP4 + d0] = i0a;
        o4[ib4 + 1 * NP4 + d0] = i1a;
        o4[ib4 + 2 * NP4 + d0] = i2a;
        o4[ib4 + 0 * NP4 + d1] = i0b;
        o4[ib4 + 1 * NP4 + d1] = i1b;
        o4[ib4 + 2 * NP4 + d1] = i2b;
        o4[LB4 + bpl4 + d0] = make_float4((float)lva.x, (float)lva.y,
                                          (float)lva.z, (float)lva.w);
        o4[LB4 + bpl4 + d1] = make_float4((float)lvb.x, (float)lvb.y,
                                          (float)lvb.z, (float)lvb.w);
        o4[CB4 + bpl4 + d0] = cva;
        o4[CB4 + bpl4 + d1] = cvb;

        // reset protocol: last scatter block for b clears flags for replay
        __syncthreads();
        if (t == 0) {
            if (atomicAdd(&g_sdone[b], 1u) == 31u) {
                g_sdone[b] = 0;
                atomicExch(&g_ready[b], 0u);
            }
        }
    }
}

extern "C" void kernel_launch(void* const* d_in, const int* in_sizes, int n_in,
                              void* d_out, int out_size) {
    const float* oimage = (const float*)d_in[0];
    const float* aimage = (const float*)d_in[1];
    const int*   olabel = (const int*)  d_in[2];
    const int*   alabel = (const int*)  d_in[3];
    const float* oconf  = (const float*)d_in[4];
    const float* aconf  = (const float*)d_in[5];
    const float* pred   = (const float*)d_in[6];
    float* out = (float*)d_out;

    k_fused<<<NB_S1 + NB_SC, 256>>>(pred, olabel, oimage, aimage,
                                    olabel, alabel, oconf, aconf, out);
}

// round 10
// speedup vs baseline: 2.3670x; 1.0137x over previous
#include <cuda_runtime.h>

// ---------------------------------------------------------------------------
// AdaMix: self-paced patch mixing — SINGLE fused kernel (R10).
//   R9 + __launch_bounds__(256,4): regs 71->64 (R6 proved no spill at 64),
//   4 CTA/SM, occupancy 33.7% -> ~50% to close the DRAM% gap.
//   blocks [0,512):     dice partials (8 seg/sample)
//   blocks [512,1536):  per-patch conf means
//     -> 24th arriving block per sample computes loss->k, rank-sort, g_map,
//        then releases g_ready[b].
//   blocks [1536,3584): gather/scatter; spin on g_ready[b], then copy.
//   All counters self-reset for graph replay. Producers (low block idx) never
//   wait => no deadlock under in-order dispatch.
// ---------------------------------------------------------------------------

#define Bn    64
#define Cn    3
#define IMGn  256
#define NCn   4
#define Hn    32
#define Pn    64
#define TOPKn 16
#define NPIX  (IMGn * IMGn)   // 65536
#define NP4   (NPIX >> 2)     // 16384 float4 per plane
#define NSEG  8               // dice segments per sample
#define ARRIVALS (NSEG + 16)  // stage1 blocks contributing to one sample
#define NB_S1 (Bn * NSEG + 1024)   // 1536
#define NB_SC (Bn * 32)            // 2048

// scratch (allocation-free: __device__ globals; zero-init, self-resetting)
__device__ double g_part[Bn][NSEG][8];   // [0:4)=inter, [4:8)=union
__device__ float  g_omean[Bn][Pn];
__device__ float  g_amean[Bn][Pn];
__device__ int    g_map[Bn][Pn];   // bit8 = use-augmented, low 8 = src patch
__device__ unsigned int g_done[Bn];      // stage1 arrivals
__device__ unsigned int g_ready[Bn];     // map published flag
__device__ unsigned int g_sdone[Bn];     // scatter arrivals (for reset)

// per-sample map: run by all 256 threads of the winning block
__device__ __forceinline__ void do_map(int b, int t) {
    __shared__ double s8[8];
    __shared__ float  s_ko[Pn], s_ka[Pn];
    __shared__ int    s_oidx[Pn], s_aidx[Pn];
    __shared__ int    s_k;
    __shared__ float  s_sign;

    if (t < 8) {
        double v = 0.0;
        #pragma unroll
        for (int s = 0; s < NSEG; s++) v += g_part[b][s][t];
        s8[t] = v;
    }
    __syncthreads();
    if (t == 0) {
        double dice = 0.0;
        #pragma unroll
        for (int c = 0; c < NCn; c++)
            dice += 2.0 * s8[c] / (s8[4 + c] + 1e-5);
        float lossf = (float)(1.0 - dice * 0.25);
        bool  mask  = lossf < 1.0f;                       // AGE = 1.0
        float spw   = 1.0f - lossf / (1.0f + 1e-5f);
        s_k    = min(TOPKn, (int)fabsf(truncf((float)TOPKn * spw)));
        s_sign = mask ? -1.0f : 1.0f;
    }
    __syncthreads();
    if (t < Pn) {
        s_ko[t] =  s_sign * g_omean[b][t];
        s_ka[t] = -s_sign * g_amean[b][t];
    }
    __syncthreads();
    if (t < Pn) {
        float mo = s_ko[t], ma = s_ka[t];
        int ro = 0, ra = 0;
        #pragma unroll
        for (int q = 0; q < Pn; q++) {
            float vo = s_ko[q]; ro += (vo < mo) || (vo == mo && q < t);
            float va = s_ka[q]; ra += (va < ma) || (va == ma && q < t);
        }
        s_oidx[ro] = t;
        s_aidx[ra] = t;
    }
    __syncthreads();
    if (t < Pn) {
        int dest = s_oidx[t];
        g_map[b][dest] = (t < s_k) ? (s_aidx[t] | 256) : dest;
    }
    __syncthreads();
    if (t == 0) {
        g_done[b] = 0;               // reset for next graph replay
        __threadfence();             // publish map before raising flag
        atomicExch(&g_ready[b], 1u);
    }
}

__global__ void __launch_bounds__(256, 4)
k_fused(const float* __restrict__ pred,
        const int*   __restrict__ olabel,
        const float* __restrict__ oimg,
        const float* __restrict__ aimg,
        const int*   __restrict__ olab,
        const int*   __restrict__ alab,
        const float* __restrict__ oconf,
        const float* __restrict__ aconf,
        float* __restrict__ out) {
    const int blk = blockIdx.x;
    const int t   = threadIdx.x;

    if (blk < Bn * NSEG) {
        // ================= dice partials: b = blk>>3, seg = blk&7 ==========
        const int b   = blk >> 3;
        const int seg = blk & (NSEG - 1);
        const float4* p4 = (const float4*)(pred + (size_t)b * NCn * NPIX);
        const int4*   l4 = (const int4*)(olabel + (size_t)b * NPIX);
        const int base4 = seg * 2048;

        float inter[NCn] = {0, 0, 0, 0};
        float uni[NCn]   = {0, 0, 0, 0};

        #pragma unroll
        for (int it = 0; it < 4; it++) {
            const int i4a = base4 + it * 512 + t;
            const int i4b = i4a + 256;
            float4 a0 = p4[i4a];
            float4 a1 = p4[i4a + NP4];
            float4 a2 = p4[i4a + 2 * NP4];
            float4 a3 = p4[i4a + 3 * NP4];
            int4   lA = l4[i4a];
            float4 b0 = p4[i4b];
            float4 b1 = p4[i4b + NP4];
            float4 b2 = p4[i4b + 2 * NP4];
            float4 b3 = p4[i4b + 3 * NP4];
            int4   lB = l4[i4b];

            #pragma unroll
            for (int g = 0; g < 2; g++) {
                float x0[4], x1[4], x2[4], x3[4];
                int   lv[4];
                if (g == 0) {
                    x0[0]=a0.x; x0[1]=a0.y; x0[2]=a0.z; x0[3]=a0.w;
                    x1[0]=a1.x; x1[1]=a1.y; x1[2]=a1.z; x1[3]=a1.w;
                    x2[0]=a2.x; x2[1]=a2.y; x2[2]=a2.z; x2[3]=a2.w;
                    x3[0]=a3.x; x3[1]=a3.y; x3[2]=a3.z; x3[3]=a3.w;
                    lv[0]=lA.x; lv[1]=lA.y; lv[2]=lA.z; lv[3]=lA.w;
                } else {
                    x0[0]=b0.x; x0[1]=b0.y; x0[2]=b0.z; x0[3]=b0.w;
                    x1[0]=b1.x; x1[1]=b1.y; x1[2]=b1.z; x1[3]=b1.w;
                    x2[0]=b2.x; x2[1]=b2.y; x2[2]=b2.z; x2[3]=b2.w;
                    x3[0]=b3.x; x3[1]=b3.y; x3[2]=b3.z; x3[3]=b3.w;
                    lv[0]=lB.x; lv[1]=lB.y; lv[2]=lB.z; lv[3]=lB.w;
                }
                #pragma unroll
                for (int j = 0; j < 4; j++) {
                    float e0 = __expf(x0[j]), e1 = __expf(x1[j]);
                    float e2 = __expf(x2[j]), e3 = __expf(x3[j]);
                    float inv = __frcp_rn((e0 + e1) + (e2 + e3));
                    float s[NCn] = {e0 * inv, e1 * inv, e2 * inv, e3 * inv};
                    const int lab = lv[j];
                    #pragma unroll
                    for (int c = 0; c < NCn; c++) {
                        float f = (lab == c) ? 1.0f : 0.0f;
                        inter[c] = fmaf(f, s[c], inter[c]);
                        uni[c]  += s[c] + f;
                    }
                }
            }
        }

        __shared__ float sred[8][256];
        #pragma unroll
        for (int q = 0; q < NCn; q++) {
            sred[q][t]     = inter[q];
            sred[4 + q][t] = uni[q];
        }
        __syncthreads();
        const int w = t >> 5, lane = t & 31;
        float v = sred[w][lane];
        #pragma unroll
        for (int j = 1; j < 8; j++) v += sred[w][lane + 32 * j];
        #pragma unroll
        for (int o = 16; o > 0; o >>= 1) v += __shfl_down_sync(0xffffffffu, v, o);
        if (lane == 0) g_part[b][seg][w] = (double)v;

        // arrival
        __syncthreads();
        __threadfence();
        __shared__ int s_win;
        if (t == 0)
            s_win = (atomicAdd(&g_done[b], 1u) == ARRIVALS - 1) ? 1 : 0;
        __syncthreads();
        if (s_win) { __threadfence(); do_map(b, t); }

    } else if (blk < NB_S1) {
        // ================= patch means ======================================
        const int m    = blk - Bn * NSEG;
        const int b    = m >> 4;
        const int s    = (m >> 3) & 1;
        const int band = m & 7;
        const float4* src = (const float4*)((s ? aconf : oconf)
                              + (size_t)b * NPIX + band * Hn * IMGn);
        float acc = 0.0f;
        #pragma unroll
        for (int it = 0; it < 8; it++) {
            float4 v = src[it * 256 + t];
            acc += (v.x + v.y) + (v.z + v.w);
        }
        __shared__ float sacc[256];
        sacc[t] = acc;
        __syncthreads();
        if (t < 8) {
            float tot = 0.0f;
            #pragma unroll
            for (int g = 0; g < 4; g++)
                #pragma unroll
                for (int j = 0; j < 8; j++)
                    tot += sacc[g * 64 + t * 8 + j];
            float mean = tot * (1.0f / (Hn * Hn));
            if (s) g_amean[b][band * 8 + t] = mean;
            else   g_omean[b][band * 8 + t] = mean;
        }

        // arrival
        __syncthreads();
        __threadfence();
        __shared__ int s_win;
        if (t == 0)
            s_win = (atomicAdd(&g_done[b], 1u) == ARRIVALS - 1) ? 1 : 0;
        __syncthreads();
        if (s_win) { __threadfence(); do_map(b, t); }

    } else {
        // ================= scatter: wait for map, then copy =================
        const int m    = blk - NB_S1;
        const int b    = m >> 5;
        const int band = m & 31;

        if (t == 0) {
            while (atomicAdd(&g_ready[b], 0u) == 0u) __nanosleep(64);
        }
        __syncthreads();
        __threadfence();   // acquire: map visible

        const int r  = t >> 6;
        const int c4 = t & 63;
        const int x  = c4 << 2;
        const int y0 = (band << 3) + r;
        const int p  = ((y0 >> 5) << 3) | (x >> 5);

        const int v    = *(volatile int*)&g_map[b][p];   // bypass L1
        const int q    = v & 255;
        const bool sel = (v & 256) != 0;
        const int sy0 = ((q >> 3) << 5) | (y0 & 31);
        const int sx  = ((q & 7)  << 5) | (x & 31);

        const size_t d0 = (size_t)y0 * 64 + c4;
        const size_t d1 = d0 + 4 * 64;
        const size_t s0 = ((size_t)sy0 * IMGn + sx) >> 2;
        const size_t s1 = s0 + 4 * 64;
        const size_t bpl4 = (size_t)b * NP4;

        const float4* img4 = (const float4*)(sel ? aimg : oimg);
        const int4*   lab4 = (const int4*)  (sel ? alab : olab);
        const float4* cnf4 = (const float4*)(sel ? aconf : oconf);
        float4* o4 = (float4*)out;

        const size_t ib4 = (size_t)b * Cn * NP4;
        const size_t LB4 = (size_t)Bn * Cn * NP4;
        const size_t CB4 = LB4 + (size_t)Bn * NP4;

        float4 i0a = img4[ib4 + 0 * NP4 + s0];
        float4 i1a = img4[ib4 + 1 * NP4 + s0];
        float4 i2a = img4[ib4 + 2 * NP4 + s0];
        float4 i0b = img4[ib4 + 0 * NP4 + s1];
        float4 i1b = img4[ib4 + 1 * NP4 + s1];
        float4 i2b = img4[ib4 + 2 * NP4 + s1];
        int4   lva = lab4[bpl4 + s0];
        int4   lvb = lab4[bpl4 + s1];
        float4 cva = cnf4[bpl4 + s0];
        float4 cvb = cnf4[bpl4 + s1];

        o4[ib4 + 0 * NP4 + d0] = i0a;
        o4[ib4 + 1 * NP4 + d0] = i1a;
        o4[ib4 + 2 * NP4 + d0] = i2a;
        o4[ib4 + 0 * NP4 + d1] = i0b;
        o4[ib4 + 1 * NP4 + d1] = i1b;
        o4[ib4 + 2 * NP4 + d1] = i2b;
        o4[LB4 + bpl4 + d0] = make_float4((float)lva.x, (float)lva.y,
                                          (float)lva.z, (float)lva.w);
        o4[LB4 + bpl4 + d1] = make_float4((float)lvb.x, (float)lvb.y,
                                          (float)lvb.z, (float)lvb.w);
        o4[CB4 + bpl4 + d0] = cva;
        o4[CB4 + bpl4 + d1] = cvb;

        // reset protocol: last scatter block for b clears flags for replay
        __syncthreads();
        if (t == 0) {
            if (atomicAdd(&g_sdone[b], 1u) == 31u) {
                g_sdone[b] = 0;
                atomicExch(&g_ready[b], 0u);
            }
        }
    }
}

extern "C" void kernel_launch(void* const* d_in, const int* in_sizes, int n_in,
                              void* d_out, int out_size) {
    const float* oimage = (const float*)d_in[0];
    const float* aimage = (const float*)d_in[1];
    const int*   olabel = (const int*)  d_in[2];
    const int*   alabel = (const int*)  d_in[3];
    const float* oconf  = (const float*)d_in[4];
    const float* aconf  = (const float*)d_in[5];
    const float* pred   = (const float*)d_in[6];
    float* out = (float*)d_out;

    k_fused<<<NB_S1 + NB_SC, 256>>>(pred, olabel, oimage, aimage,
                                    olabel, alabel, oconf, aconf, out);
}

// round 11
// speedup vs baseline: 2.5778x; 1.0891x over previous
#include <cuda_runtime.h>

// ---------------------------------------------------------------------------
// AdaMix: self-paced patch mixing — SINGLE fused kernel (R11).
//   R10 + cache-policy traffic cut: all single-use streams (pred, images,
//   output) use evict-first (.cs) so the twice-read labels/conf (48 MB)
//   survive in L2 from stage1 to scatter.
//   blocks [0,512):     dice partials (8 seg/sample)
//   blocks [512,1536):  per-patch conf means
//     -> 24th arriving block per sample computes loss->k, rank-sort, g_map
//   blocks [1536,3584): gather/scatter; spin on g_ready[b], then copy.
// ---------------------------------------------------------------------------

#define Bn    64
#define Cn    3
#define IMGn  256
#define NCn   4
#define Hn    32
#define Pn    64
#define TOPKn 16
#define NPIX  (IMGn * IMGn)   // 65536
#define NP4   (NPIX >> 2)     // 16384 float4 per plane
#define NSEG  8               // dice segments per sample
#define ARRIVALS (NSEG + 16)  // stage1 blocks contributing to one sample
#define NB_S1 (Bn * NSEG + 1024)   // 1536
#define NB_SC (Bn * 32)            // 2048

// scratch (allocation-free: __device__ globals; zero-init, self-resetting)
__device__ double g_part[Bn][NSEG][8];   // [0:4)=inter, [4:8)=union
__device__ float  g_omean[Bn][Pn];
__device__ float  g_amean[Bn][Pn];
__device__ int    g_map[Bn][Pn];   // bit8 = use-augmented, low 8 = src patch
__device__ unsigned int g_done[Bn];      // stage1 arrivals
__device__ unsigned int g_ready[Bn];     // map published flag
__device__ unsigned int g_sdone[Bn];     // scatter arrivals (for reset)

// per-sample map: run by all 256 threads of the winning block
__device__ __forceinline__ void do_map(int b, int t) {
    __shared__ double s8[8];
    __shared__ float  s_ko[Pn], s_ka[Pn];
    __shared__ int    s_oidx[Pn], s_aidx[Pn];
    __shared__ int    s_k;
    __shared__ float  s_sign;

    if (t < 8) {
        double v = 0.0;
        #pragma unroll
        for (int s = 0; s < NSEG; s++) v += g_part[b][s][t];
        s8[t] = v;
    }
    __syncthreads();
    if (t == 0) {
        double dice = 0.0;
        #pragma unroll
        for (int c = 0; c < NCn; c++)
            dice += 2.0 * s8[c] / (s8[4 + c] + 1e-5);
        float lossf = (float)(1.0 - dice * 0.25);
        bool  mask  = lossf < 1.0f;                       // AGE = 1.0
        float spw   = 1.0f - lossf / (1.0f + 1e-5f);
        s_k    = min(TOPKn, (int)fabsf(truncf((float)TOPKn * spw)));
        s_sign = mask ? -1.0f : 1.0f;
    }
    __syncthreads();
    if (t < Pn) {
        s_ko[t] =  s_sign * g_omean[b][t];
        s_ka[t] = -s_sign * g_amean[b][t];
    }
    __syncthreads();
    if (t < Pn) {
        float mo = s_ko[t], ma = s_ka[t];
        int ro = 0, ra = 0;
        #pragma unroll
        for (int q = 0; q < Pn; q++) {
            float vo = s_ko[q]; ro += (vo < mo) || (vo == mo && q < t);
            float va = s_ka[q]; ra += (va < ma) || (va == ma && q < t);
        }
        s_oidx[ro] = t;
        s_aidx[ra] = t;
    }
    __syncthreads();
    if (t < Pn) {
        int dest = s_oidx[t];
        g_map[b][dest] = (t < s_k) ? (s_aidx[t] | 256) : dest;
    }
    __syncthreads();
    if (t == 0) {
        g_done[b] = 0;               // reset for next graph replay
        __threadfence();             // publish map before raising flag
        atomicExch(&g_ready[b], 1u);
    }
}

__global__ void __launch_bounds__(256, 4)
k_fused(const float* __restrict__ pred,
        const int*   __restrict__ olabel,
        const float* __restrict__ oimg,
        const float* __restrict__ aimg,
        const int*   __restrict__ olab,
        const int*   __restrict__ alab,
        const float* __restrict__ oconf,
        const float* __restrict__ aconf,
        float* __restrict__ out) {
    const int blk = blockIdx.x;
    const int t   = threadIdx.x;

    if (blk < Bn * NSEG) {
        // ================= dice partials: b = blk>>3, seg = blk&7 ==========
        const int b   = blk >> 3;
        const int seg = blk & (NSEG - 1);
        const float4* p4 = (const float4*)(pred + (size_t)b * NCn * NPIX);
        const int4*   l4 = (const int4*)(olabel + (size_t)b * NPIX);
        const int base4 = seg * 2048;

        float inter[NCn] = {0, 0, 0, 0};
        float uni[NCn]   = {0, 0, 0, 0};

        #pragma unroll
        for (int it = 0; it < 4; it++) {
            const int i4a = base4 + it * 512 + t;
            const int i4b = i4a + 256;
            // pred: single-use -> streaming loads; labels: keep in L2 (reused
            // by scatter) -> default policy.
            float4 a0 = __ldcs(&p4[i4a]);
            float4 a1 = __ldcs(&p4[i4a + NP4]);
            float4 a2 = __ldcs(&p4[i4a + 2 * NP4]);
            float4 a3 = __ldcs(&p4[i4a + 3 * NP4]);
            int4   lA = l4[i4a];
            float4 b0 = __ldcs(&p4[i4b]);
            float4 b1 = __ldcs(&p4[i4b + NP4]);
            float4 b2 = __ldcs(&p4[i4b + 2 * NP4]);
            float4 b3 = __ldcs(&p4[i4b + 3 * NP4]);
            int4   lB = l4[i4b];

            #pragma unroll
            for (int g = 0; g < 2; g++) {
                float x0[4], x1[4], x2[4], x3[4];
                int   lv[4];
                if (g == 0) {
                    x0[0]=a0.x; x0[1]=a0.y; x0[2]=a0.z; x0[3]=a0.w;
                    x1[0]=a1.x; x1[1]=a1.y; x1[2]=a1.z; x1[3]=a1.w;
                    x2[0]=a2.x; x2[1]=a2.y; x2[2]=a2.z; x2[3]=a2.w;
                    x3[0]=a3.x; x3[1]=a3.y; x3[2]=a3.z; x3[3]=a3.w;
                    lv[0]=lA.x; lv[1]=lA.y; lv[2]=lA.z; lv[3]=lA.w;
                } else {
                    x0[0]=b0.x; x0[1]=b0.y; x0[2]=b0.z; x0[3]=b0.w;
                    x1[0]=b1.x; x1[1]=b1.y; x1[2]=b1.z; x1[3]=b1.w;
                    x2[0]=b2.x; x2[1]=b2.y; x2[2]=b2.z; x2[3]=b2.w;
                    x3[0]=b3.x; x3[1]=b3.y; x3[2]=b3.z; x3[3]=b3.w;
                    lv[0]=lB.x; lv[1]=lB.y; lv[2]=lB.z; lv[3]=lB.w;
                }
                #pragma unroll
                for (int j = 0; j < 4; j++) {
                    float e0 = __expf(x0[j]), e1 = __expf(x1[j]);
                    float e2 = __expf(x2[j]), e3 = __expf(x3[j]);
                    float inv = __frcp_rn((e0 + e1) + (e2 + e3));
                    float s[NCn] = {e0 * inv, e1 * inv, e2 * inv, e3 * inv};
                    const int lab = lv[j];
                    #pragma unroll
                    for (int c = 0; c < NCn; c++) {
                        float f = (lab == c) ? 1.0f : 0.0f;
                        inter[c] = fmaf(f, s[c], inter[c]);
                        uni[c]  += s[c] + f;
                    }
                }
            }
        }

        __shared__ float sred[8][256];
        #pragma unroll
        for (int q = 0; q < NCn; q++) {
            sred[q][t]     = inter[q];
            sred[4 + q][t] = uni[q];
        }
        __syncthreads();
        const int w = t >> 5, lane = t & 31;
        float v = sred[w][lane];
        #pragma unroll
        for (int j = 1; j < 8; j++) v += sred[w][lane + 32 * j];
        #pragma unroll
        for (int o = 16; o > 0; o >>= 1) v += __shfl_down_sync(0xffffffffu, v, o);
        if (lane == 0) g_part[b][seg][w] = (double)v;

        // arrival
        __syncthreads();
        __threadfence();
        __shared__ int s_win;
        if (t == 0)
            s_win = (atomicAdd(&g_done[b], 1u) == ARRIVALS - 1) ? 1 : 0;
        __syncthreads();
        if (s_win) { __threadfence(); do_map(b, t); }

    } else if (blk < NB_S1) {
        // ================= patch means (conf: default policy, reused) =======
        const int m    = blk - Bn * NSEG;
        const int b    = m >> 4;
        const int s    = (m >> 3) & 1;
        const int band = m & 7;
        const float4* src = (const float4*)((s ? aconf : oconf)
                              + (size_t)b * NPIX + band * Hn * IMGn);
        float acc = 0.0f;
        #pragma unroll
        for (int it = 0; it < 8; it++) {
            float4 v = src[it * 256 + t];
            acc += (v.x + v.y) + (v.z + v.w);
        }
        __shared__ float sacc[256];
        sacc[t] = acc;
        __syncthreads();
        if (t < 8) {
            float tot = 0.0f;
            #pragma unroll
            for (int g = 0; g < 4; g++)
                #pragma unroll
                for (int j = 0; j < 8; j++)
                    tot += sacc[g * 64 + t * 8 + j];
            float mean = tot * (1.0f / (Hn * Hn));
            if (s) g_amean[b][band * 8 + t] = mean;
            else   g_omean[b][band * 8 + t] = mean;
        }

        // arrival
        __syncthreads();
        __threadfence();
        __shared__ int s_win;
        if (t == 0)
            s_win = (atomicAdd(&g_done[b], 1u) == ARRIVALS - 1) ? 1 : 0;
        __syncthreads();
        if (s_win) { __threadfence(); do_map(b, t); }

    } else {
        // ================= scatter: wait for map, then copy =================
        const int m    = blk - NB_S1;
        const int b    = m >> 5;
        const int band = m & 31;

        if (t == 0) {
            while (atomicAdd(&g_ready[b], 0u) == 0u) __nanosleep(64);
        }
        __syncthreads();
        __threadfence();   // acquire: map visible

        const int r  = t >> 6;
        const int c4 = t & 63;
        const int x  = c4 << 2;
        const int y0 = (band << 3) + r;
        const int p  = ((y0 >> 5) << 3) | (x >> 5);

        const int v    = *(volatile int*)&g_map[b][p];   // bypass L1
        const int q    = v & 255;
        const bool sel = (v & 256) != 0;
        const int sy0 = ((q >> 3) << 5) | (y0 & 31);
        const int sx  = ((q & 7)  << 5) | (x & 31);

        const size_t d0 = (size_t)y0 * 64 + c4;
        const size_t d1 = d0 + 4 * 64;
        const size_t s0 = ((size_t)sy0 * IMGn + sx) >> 2;
        const size_t s1 = s0 + 4 * 64;
        const size_t bpl4 = (size_t)b * NP4;

        const float4* img4 = (const float4*)(sel ? aimg : oimg);
        const int4*   lab4 = (const int4*)  (sel ? alab : olab);
        const float4* cnf4 = (const float4*)(sel ? aconf : oconf);
        float4* o4 = (float4*)out;

        const size_t ib4 = (size_t)b * Cn * NP4;
        const size_t LB4 = (size_t)Bn * Cn * NP4;
        const size_t CB4 = LB4 + (size_t)Bn * NP4;

        // images: single-use -> streaming; conf/labels: hope for L2 hits
        float4 i0a = __ldcs(&img4[ib4 + 0 * NP4 + s0]);
        float4 i1a = __ldcs(&img4[ib4 + 1 * NP4 + s0]);
        float4 i2a = __ldcs(&img4[ib4 + 2 * NP4 + s0]);
        float4 i0b = __ldcs(&img4[ib4 + 0 * NP4 + s1]);
        float4 i1b = __ldcs(&img4[ib4 + 1 * NP4 + s1]);
        float4 i2b = __ldcs(&img4[ib4 + 2 * NP4 + s1]);
        int4   lva = lab4[bpl4 + s0];
        int4   lvb = lab4[bpl4 + s1];
        float4 cva = cnf4[bpl4 + s0];
        float4 cvb = cnf4[bpl4 + s1];

        // output: single-use -> streaming stores (don't pollute L2)
        __stcs(&o4[ib4 + 0 * NP4 + d0], i0a);
        __stcs(&o4[ib4 + 1 * NP4 + d0], i1a);
        __stcs(&o4[ib4 + 2 * NP4 + d0], i2a);
        __stcs(&o4[ib4 + 0 * NP4 + d1], i0b);
        __stcs(&o4[ib4 + 1 * NP4 + d1], i1b);
        __stcs(&o4[ib4 + 2 * NP4 + d1], i2b);
        __stcs(&o4[LB4 + bpl4 + d0], make_float4((float)lva.x, (float)lva.y,
                                                 (float)lva.z, (float)lva.w));
        __stcs(&o4[LB4 + bpl4 + d1], make_float4((float)lvb.x, (float)lvb.y,
                                                 (float)lvb.z, (float)lvb.w));
        __stcs(&o4[CB4 + bpl4 + d0], cva);
        __stcs(&o4[CB4 + bpl4 + d1], cvb);

        // reset protocol: last scatter block for b clears flags for replay
        __syncthreads();
        if (t == 0) {
            if (atomicAdd(&g_sdone[b], 1u) == 31u) {
                g_sdone[b] = 0;
                atomicExch(&g_ready[b], 0u);
            }
        }
    }
}

extern "C" void kernel_launch(void* const* d_in, const int* in_sizes, int n_in,
                              void* d_out, int out_size) {
    const float* oimage = (const float*)d_in[0];
    const float* aimage = (const float*)d_in[1];
    const int*   olabel = (const int*)  d_in[2];
    const int*   alabel = (const int*)  d_in[3];
    const float* oconf  = (const float*)d_in[4];
    const float* aconf  = (const float*)d_in[5];
    const float* pred   = (const float*)d_in[6];
    float* out = (float*)d_out;

    k_fused<<<NB_S1 + NB_SC, 256>>>(pred, olabel, oimage, aimage,
                                    olabel, alabel, oconf, aconf, out);
}

// round 12
// speedup vs baseline: 2.6152x; 1.0145x over previous
#include <cuda_runtime.h>

// ---------------------------------------------------------------------------
// AdaMix: self-paced patch mixing — SINGLE fused kernel (R12).
//   R11 + scatter consolidation: 1024 scatter blocks (16 dest rows each),
//   each thread copies 4 rows in two pipelined batches of 10 loads/10 stores.
//   Halves scatter block-overhead (spin, map load, reset) at equal regs.
//   blocks [0,512):     dice partials (8 seg/sample)
//   blocks [512,1536):  per-patch conf means
//     -> 24th arriving block per sample computes loss->k, rank-sort, g_map
//   blocks [1536,2560): gather/scatter; spin on g_ready[b], then copy.
// ---------------------------------------------------------------------------

#define Bn    64
#define Cn    3
#define IMGn  256
#define NCn   4
#define Hn    32
#define Pn    64
#define TOPKn 16
#define NPIX  (IMGn * IMGn)   // 65536
#define NP4   (NPIX >> 2)     // 16384 float4 per plane
#define NSEG  8               // dice segments per sample
#define ARRIVALS (NSEG + 16)  // stage1 blocks contributing to one sample
#define NB_S1 (Bn * NSEG + 1024)   // 1536
#define NB_SC (Bn * 16)            // 1024 scatter blocks (16 rows each)

// scratch (allocation-free: __device__ globals; zero-init, self-resetting)
__device__ double g_part[Bn][NSEG][8];   // [0:4)=inter, [4:8)=union
__device__ float  g_omean[Bn][Pn];
__device__ float  g_amean[Bn][Pn];
__device__ int    g_map[Bn][Pn];   // bit8 = use-augmented, low 8 = src patch
__device__ unsigned int g_done[Bn];      // stage1 arrivals
__device__ unsigned int g_ready[Bn];     // map published flag
__device__ unsigned int g_sdone[Bn];     // scatter arrivals (for reset)

// per-sample map: run by all 256 threads of the winning block
__device__ __forceinline__ void do_map(int b, int t) {
    __shared__ double s8[8];
    __shared__ float  s_ko[Pn], s_ka[Pn];
    __shared__ int    s_oidx[Pn], s_aidx[Pn];
    __shared__ int    s_k;
    __shared__ float  s_sign;

    if (t < 8) {
        double v = 0.0;
        #pragma unroll
        for (int s = 0; s < NSEG; s++) v += g_part[b][s][t];
        s8[t] = v;
    }
    __syncthreads();
    if (t == 0) {
        double dice = 0.0;
        #pragma unroll
        for (int c = 0; c < NCn; c++)
            dice += 2.0 * s8[c] / (s8[4 + c] + 1e-5);
        float lossf = (float)(1.0 - dice * 0.25);
        bool  mask  = lossf < 1.0f;                       // AGE = 1.0
        float spw   = 1.0f - lossf / (1.0f + 1e-5f);
        s_k    = min(TOPKn, (int)fabsf(truncf((float)TOPKn * spw)));
        s_sign = mask ? -1.0f : 1.0f;
    }
    __syncthreads();
    if (t < Pn) {
        s_ko[t] =  s_sign * g_omean[b][t];
        s_ka[t] = -s_sign * g_amean[b][t];
    }
    __syncthreads();
    if (t < Pn) {
        float mo = s_ko[t], ma = s_ka[t];
        int ro = 0, ra = 0;
        #pragma unroll
        for (int q = 0; q < Pn; q++) {
            float vo = s_ko[q]; ro += (vo < mo) || (vo == mo && q < t);
            float va = s_ka[q]; ra += (va < ma) || (va == ma && q < t);
        }
        s_oidx[ro] = t;
        s_aidx[ra] = t;
    }
    __syncthreads();
    if (t < Pn) {
        int dest = s_oidx[t];
        g_map[b][dest] = (t < s_k) ? (s_aidx[t] | 256) : dest;
    }
    __syncthreads();
    if (t == 0) {
        g_done[b] = 0;               // reset for next graph replay
        __threadfence();             // publish map before raising flag
        atomicExch(&g_ready[b], 1u);
    }
}

__global__ void __launch_bounds__(256, 4)
k_fused(const float* __restrict__ pred,
        const int*   __restrict__ olabel,
        const float* __restrict__ oimg,
        const float* __restrict__ aimg,
        const int*   __restrict__ olab,
        const int*   __restrict__ alab,
        const float* __restrict__ oconf,
        const float* __restrict__ aconf,
        float* __restrict__ out) {
    const int blk = blockIdx.x;
    const int t   = threadIdx.x;

    if (blk < Bn * NSEG) {
        // ================= dice partials: b = blk>>3, seg = blk&7 ==========
        const int b   = blk >> 3;
        const int seg = blk & (NSEG - 1);
        const float4* p4 = (const float4*)(pred + (size_t)b * NCn * NPIX);
        const int4*   l4 = (const int4*)(olabel + (size_t)b * NPIX);
        const int base4 = seg * 2048;

        float inter[NCn] = {0, 0, 0, 0};
        float uni[NCn]   = {0, 0, 0, 0};

        #pragma unroll
        for (int it = 0; it < 4; it++) {
            const int i4a = base4 + it * 512 + t;
            const int i4b = i4a + 256;
            // pred: single-use -> streaming; labels: default (reused by scatter)
            float4 a0 = __ldcs(&p4[i4a]);
            float4 a1 = __ldcs(&p4[i4a + NP4]);
            float4 a2 = __ldcs(&p4[i4a + 2 * NP4]);
            float4 a3 = __ldcs(&p4[i4a + 3 * NP4]);
            int4   lA = l4[i4a];
            float4 b0 = __ldcs(&p4[i4b]);
            float4 b1 = __ldcs(&p4[i4b + NP4]);
            float4 b2 = __ldcs(&p4[i4b + 2 * NP4]);
            float4 b3 = __ldcs(&p4[i4b + 3 * NP4]);
            int4   lB = l4[i4b];

            #pragma unroll
            for (int g = 0; g < 2; g++) {
                float x0[4], x1[4], x2[4], x3[4];
                int   lv[4];
                if (g == 0) {
                    x0[0]=a0.x; x0[1]=a0.y; x0[2]=a0.z; x0[3]=a0.w;
                    x1[0]=a1.x; x1[1]=a1.y; x1[2]=a1.z; x1[3]=a1.w;
                    x2[0]=a2.x; x2[1]=a2.y; x2[2]=a2.z; x2[3]=a2.w;
                    x3[0]=a3.x; x3[1]=a3.y; x3[2]=a3.z; x3[3]=a3.w;
                    lv[0]=lA.x; lv[1]=lA.y; lv[2]=lA.z; lv[3]=lA.w;
                } else {
                    x0[0]=b0.x; x0[1]=b0.y; x0[2]=b0.z; x0[3]=b0.w;
                    x1[0]=b1.x; x1[1]=b1.y; x1[2]=b1.z; x1[3]=b1.w;
                    x2[0]=b2.x; x2[1]=b2.y; x2[2]=b2.z; x2[3]=b2.w;
                    x3[0]=b3.x; x3[1]=b3.y; x3[2]=b3.z; x3[3]=b3.w;
                    lv[0]=lB.x; lv[1]=lB.y; lv[2]=lB.z; lv[3]=lB.w;
                }
                #pragma unroll
                for (int j = 0; j < 4; j++) {
                    float e0 = __expf(x0[j]), e1 = __expf(x1[j]);
                    float e2 = __expf(x2[j]), e3 = __expf(x3[j]);
                    float inv = __frcp_rn((e0 + e1) + (e2 + e3));
                    float s[NCn] = {e0 * inv, e1 * inv, e2 * inv, e3 * inv};
                    const int lab = lv[j];
                    #pragma unroll
                    for (int c = 0; c < NCn; c++) {
                        float f = (lab == c) ? 1.0f : 0.0f;
                        inter[c] = fmaf(f, s[c], inter[c]);
                        uni[c]  += s[c] + f;
                    }
                }
            }
        }

        __shared__ float sred[8][256];
        #pragma unroll
        for (int q = 0; q < NCn; q++) {
            sred[q][t]     = inter[q];
            sred[4 + q][t] = uni[q];
        }
        __syncthreads();
        const int w = t >> 5, lane = t & 31;
        float v = sred[w][lane];
        #pragma unroll
        for (int j = 1; j < 8; j++) v += sred[w][lane + 32 * j];
        #pragma unroll
        for (int o = 16; o > 0; o >>= 1) v += __shfl_down_sync(0xffffffffu, v, o);
        if (lane == 0) g_part[b][seg][w] = (double)v;

        // arrival
        __syncthreads();
        __threadfence();
        __shared__ int s_win;
        if (t == 0)
            s_win = (atomicAdd(&g_done[b], 1u) == ARRIVALS - 1) ? 1 : 0;
        __syncthreads();
        if (s_win) { __threadfence(); do_map(b, t); }

    } else if (blk < NB_S1) {
        // ================= patch means (conf: default policy, reused) =======
        const int m    = blk - Bn * NSEG;
        const int b    = m >> 4;
        const int s    = (m >> 3) & 1;
        const int band = m & 7;
        const float4* src = (const float4*)((s ? aconf : oconf)
                              + (size_t)b * NPIX + band * Hn * IMGn);
        float acc = 0.0f;
        #pragma unroll
        for (int it = 0; it < 8; it++) {
            float4 v = src[it * 256 + t];
            acc += (v.x + v.y) + (v.z + v.w);
        }
        __shared__ float sacc[256];
        sacc[t] = acc;
        __syncthreads();
        if (t < 8) {
            float tot = 0.0f;
            #pragma unroll
            for (int g = 0; g < 4; g++)
                #pragma unroll
                for (int j = 0; j < 8; j++)
                    tot += sacc[g * 64 + t * 8 + j];
            float mean = tot * (1.0f / (Hn * Hn));
            if (s) g_amean[b][band * 8 + t] = mean;
            else   g_omean[b][band * 8 + t] = mean;
        }

        // arrival
        __syncthreads();
        __threadfence();
        __shared__ int s_win;
        if (t == 0)
            s_win = (atomicAdd(&g_done[b], 1u) == ARRIVALS - 1) ? 1 : 0;
        __syncthreads();
        if (s_win) { __threadfence(); do_map(b, t); }

    } else {
        // ================= scatter: wait for map, then copy 16 rows =========
        const int m    = blk - NB_S1;
        const int b    = m >> 4;
        const int band = m & 15;            // 16 dest rows: band*16..band*16+15

        if (t == 0) {
            while (atomicAdd(&g_ready[b], 0u) == 0u) __nanosleep(64);
        }
        __syncthreads();
        __threadfence();   // acquire: map visible

        const int r  = t >> 6;              // 0..3
        const int c4 = t & 63;
        const int x  = c4 << 2;
        const int y0 = (band << 4) + r;     // rows y0, +4, +8, +12 (same patch)
        const int p  = ((y0 >> 5) << 3) | (x >> 5);

        const int v    = *(volatile int*)&g_map[b][p];   // bypass L1
        const int q    = v & 255;
        const bool sel = (v & 256) != 0;
        const int sx   = ((q & 7) << 5) | (x & 31);
        const int qy   = (q >> 3) << 5;

        const size_t bpl4 = (size_t)b * NP4;
        const float4* img4 = (const float4*)(sel ? aimg : oimg);
        const int4*   lab4 = (const int4*)  (sel ? alab : olab);
        const float4* cnf4 = (const float4*)(sel ? aconf : oconf);
        float4* o4 = (float4*)out;

        const size_t ib4 = (size_t)b * Cn * NP4;
        const size_t LB4 = (size_t)Bn * Cn * NP4;
        const size_t CB4 = LB4 + (size_t)Bn * NP4;

        #pragma unroll
        for (int half = 0; half < 2; half++) {
            const int yA = y0 + half * 8;            // rows yA and yA+4
            const size_t d0 = (size_t)yA * 64 + c4;
            const size_t d1 = d0 + 4 * 64;
            const size_t s0 = ((size_t)(qy | (yA & 31)) * IMGn + sx) >> 2;
            const size_t s1 = s0 + 4 * 64;

            // batch: 10 loads in flight, then 10 streaming stores
            float4 i0a = __ldcs(&img4[ib4 + 0 * NP4 + s0]);
            float4 i1a = __ldcs(&img4[ib4 + 1 * NP4 + s0]);
            float4 i2a = __ldcs(&img4[ib4 + 2 * NP4 + s0]);
            float4 i0b = __ldcs(&img4[ib4 + 0 * NP4 + s1]);
            float4 i1b = __ldcs(&img4[ib4 + 1 * NP4 + s1]);
            float4 i2b = __ldcs(&img4[ib4 + 2 * NP4 + s1]);
            int4   lva = lab4[bpl4 + s0];
            int4   lvb = lab4[bpl4 + s1];
            float4 cva = cnf4[bpl4 + s0];
            float4 cvb = cnf4[bpl4 + s1];

            __stcs(&o4[ib4 + 0 * NP4 + d0], i0a);
            __stcs(&o4[ib4 + 1 * NP4 + d0], i1a);
            __stcs(&o4[ib4 + 2 * NP4 + d0], i2a);
            __stcs(&o4[ib4 + 0 * NP4 + d1], i0b);
            __stcs(&o4[ib4 + 1 * NP4 + d1], i1b);
            __stcs(&o4[ib4 + 2 * NP4 + d1], i2b);
            __stcs(&o4[LB4 + bpl4 + d0],
                   make_float4((float)lva.x, (float)lva.y,
                               (float)lva.z, (float)lva.w));
            __stcs(&o4[LB4 + bpl4 + d1],
                   make_float4((float)lvb.x, (float)lvb.y,
                               (float)lvb.z, (float)lvb.w));
            __stcs(&o4[CB4 + bpl4 + d0], cva);
            __stcs(&o4[CB4 + bpl4 + d1], cvb);
        }

        // reset protocol: last scatter block for b clears flags for replay
        __syncthreads();
        if (t == 0) {
            if (atomicAdd(&g_sdone[b], 1u) == 15u) {
                g_sdone[b] = 0;
                atomicExch(&g_ready[b], 0u);
            }
        }
    }
}

extern "C" void kernel_launch(void* const* d_in, const int* in_sizes, int n_in,
                              void* d_out, int out_size) {
    const float* oimage = (const float*)d_in[0];
    const float* aimage = (const float*)d_in[1];
    const int*   olabel = (const int*)  d_in[2];
    const int*   alabel = (const int*)  d_in[3];
    const float* oconf  = (const float*)d_in[4];
    const float* aconf  = (const float*)d_in[5];
    const float* pred   = (const float*)d_in[6];
    float* out = (float*)d_out;

    k_fused<<<NB_S1 + NB_SC, 256>>>(pred, olabel, oimage, aimage,
                                    olabel, alabel, oconf, aconf, out);
}